// round 10
// baseline (speedup 1.0000x reference)
#include <cuda_runtime.h>
#include <cuda_bf16.h>
#include <cstdint>

#define B_ 64
#define H_ 512
#define V_ 50257
#define NPROJ 393            // ceil(V_/128)

// ---- scratch (__device__ globals; no allocation allowed) ----
__device__ float g_upart[8 * 64 * 512];      // partial u = h1 @ attn_W
__device__ float g_bctx[64 * 32 * 512];      // block contexts
__device__ float g_x0[64 * 1024];            // [embedded | context] fp32 (layer-0 input)
__device__ uint4 g_x1h4[8192];               // x1 bf16  [64][1024]
__device__ float g_gxp[16 * 64 * 1536];      // gx partials (k-split)
__device__ float g_ghp[8 * 64 * 1536];       // gh partials (k-split)
__device__ float2 g_pm[NPROJ * 64];          // per-CTA per-row (max, sumexp)
__device__ float g_lsmv[64];                 // per-row lse

// ---- output layout: log_probs, new_hidden[2,B,H], context[B,H], attn_w[B,32,64]
#define OFF_NH   ((size_t)B_ * V_)
#define OFF_CTX  (OFF_NH + (size_t)2 * B_ * H_)
#define OFF_ATTN (OFF_CTX + (size_t)B_ * H_)

// =====================================================================
// u partials: u[b,h] = sum_g h1[b,g] * attn_W[g,h]
// =====================================================================
__global__ __launch_bounds__(256) void k_u_part(const float* __restrict__ hidden,
                                                const float* __restrict__ attn_W) {
    __shared__ float Hs[64 * 65];
    __shared__ float Ws[64 * 65];
    const int t = threadIdx.x;
    const int h0 = blockIdx.x * 64, g0 = blockIdx.y * 64;
    const float* h1 = hidden + 64 * 512;  // hidden[-1]
#pragma unroll
    for (int j = 0; j < 4; ++j) {
        int lin = (t + j * 256) * 4;
        int bb = lin >> 6, kk = lin & 63;
        float4 v = *(const float4*)(h1 + (size_t)bb * 512 + g0 + kk);
        Hs[bb * 65 + kk + 0] = v.x; Hs[bb * 65 + kk + 1] = v.y;
        Hs[bb * 65 + kk + 2] = v.z; Hs[bb * 65 + kk + 3] = v.w;
    }
#pragma unroll
    for (int j = 0; j < 4; ++j) {
        int lin = (t + j * 256) * 4;
        int kk = lin >> 6, hh = lin & 63;
        float4 v = *(const float4*)(attn_W + (size_t)(g0 + kk) * 512 + h0 + hh);
        Ws[(hh + 0) * 65 + kk] = v.x; Ws[(hh + 1) * 65 + kk] = v.y;
        Ws[(hh + 2) * 65 + kk] = v.z; Ws[(hh + 3) * 65 + kk] = v.w;
    }
    __syncthreads();
    const int tb = t & 15, tc = t >> 4;
    float acc[4][4] = {};
#pragma unroll 8
    for (int kk = 0; kk < 64; ++kk) {
        float a0 = Hs[(tb * 4 + 0) * 65 + kk];
        float a1 = Hs[(tb * 4 + 1) * 65 + kk];
        float a2 = Hs[(tb * 4 + 2) * 65 + kk];
        float a3 = Hs[(tb * 4 + 3) * 65 + kk];
#pragma unroll
        for (int j = 0; j < 4; ++j) {
            float wv = Ws[(tc * 4 + j) * 65 + kk];
            acc[0][j] += a0 * wv; acc[1][j] += a1 * wv;
            acc[2][j] += a2 * wv; acc[3][j] += a3 * wv;
        }
    }
#pragma unroll
    for (int i = 0; i < 4; ++i)
#pragma unroll
        for (int j = 0; j < 4; ++j)
            g_upart[((size_t)blockIdx.y * 64 + tb * 4 + i) * 512 + h0 + tc * 4 + j] = acc[i][j];
}

// =====================================================================
// Block attention: one CTA per (b, n); tile cached in smem for 2nd pass.
// =====================================================================
__global__ __launch_bounds__(512) void k_attn(const float* __restrict__ enc,
                                              float* __restrict__ out) {
    extern __shared__ float sm[];
    float* tile = sm;                       // 64*512
    float* u_s  = sm + 64 * 512;            // 512
    float* sc   = sm + 64 * 512 + 512;      // 64
    const int t = threadIdx.x, w = t >> 5, lane = t & 31;
    const int bn = blockIdx.x;
    const int b = bn >> 5;

    {   float s = 0.f;
#pragma unroll
        for (int p = 0; p < 8; ++p) s += g_upart[((size_t)p * 64 + b) * 512 + t];
        u_s[t] = s;
    }
    __syncthreads();

    float uu[4][4];
#pragma unroll
    for (int j = 0; j < 4; ++j) {
        float4 q = *(const float4*)&u_s[(lane + 32 * j) * 4];
        uu[j][0] = q.x; uu[j][1] = q.y; uu[j][2] = q.z; uu[j][3] = q.w;
    }
    const float4* eo4 = (const float4*)(enc + (size_t)bn * (64 * 512));
    float4* tile4 = (float4*)tile;
#pragma unroll
    for (int i = 0; i < 4; ++i) {
        const int l = w * 4 + i;
        float acc = 0.f;
#pragma unroll
        for (int j = 0; j < 4; ++j) {
            float4 v = eo4[l * 128 + lane + 32 * j];
            tile4[l * 128 + lane + 32 * j] = v;
            acc += v.x * uu[j][0] + v.y * uu[j][1] + v.z * uu[j][2] + v.w * uu[j][3];
        }
#pragma unroll
        for (int o = 16; o; o >>= 1) acc += __shfl_xor_sync(0xffffffffu, acc, o);
        if (lane == 0) sc[l] = acc;
    }
    __syncthreads();

    if (w == 0) {
        float s0 = sc[lane], s1 = sc[lane + 32];
        float m = fmaxf(s0, s1);
#pragma unroll
        for (int o = 16; o; o >>= 1) m = fmaxf(m, __shfl_xor_sync(0xffffffffu, m, o));
        float e0 = __expf(s0 - m), e1 = __expf(s1 - m);
        float s = e0 + e1;
#pragma unroll
        for (int o = 16; o; o >>= 1) s += __shfl_xor_sync(0xffffffffu, s, o);
        float inv = 1.f / s;
        float w0 = e0 * inv, w1 = e1 * inv;
        sc[lane] = w0; sc[lane + 32] = w1;
        out[OFF_ATTN + (size_t)bn * 64 + lane] = w0;
        out[OFF_ATTN + (size_t)bn * 64 + lane + 32] = w1;
    }
    __syncthreads();

    float acc = 0.f;
#pragma unroll 8
    for (int l = 0; l < 64; ++l) acc += sc[l] * tile[l * 512 + t];
    g_bctx[(size_t)bn * 512 + t] = acc;
}

// =====================================================================
// context reduce + embedding gather + concat inputs (+bf16 of ctx)
// =====================================================================
__global__ __launch_bounds__(512) void k_ctx(const float* __restrict__ baw,
                                             const float* __restrict__ emb,
                                             const int* __restrict__ ids,
                                             float* __restrict__ out) {
    const int b = blockIdx.x, h = threadIdx.x;
    float acc = 0.f;
#pragma unroll 8
    for (int n = 0; n < 32; ++n)
        acc += baw[b * 32 + n] * g_bctx[((size_t)b * 32 + n) * 512 + h];
    out[OFF_CTX + (size_t)b * 512 + h] = acc;
    g_x0[b * 1024 + 512 + h] = acc;
    ((__nv_bfloat16*)g_x1h4)[b * 1024 + 512 + h] = __float2bfloat16(acc);
    g_x0[b * 1024 + h] = emb[(size_t)ids[b] * 512 + h];
}

// =====================================================================
// Gate GEMM, single-shot 64-k chunk: all 12 LDG.128/thread issued before
// the (single) barrier -> max MLP, zero mid-loop stalls. fma.rn.f32x2.
// C[b,r] partial = sum_{k in [ks,ks+64)} A[b,k]*W[r,k]
// =====================================================================
__device__ __forceinline__ void ffma2(unsigned long long& d, unsigned long long a,
                                      unsigned long long b) {
    asm("fma.rn.f32x2 %0, %1, %2, %0;" : "+l"(d) : "l"(a), "l"(b));
}

#define AS64_ULL (64 * 34)
#define WD64_ULL (64 * 130)
#define GEMM_SMEM_BYTES ((AS64_ULL + WD64_ULL) * 8)   // 83968

__device__ __forceinline__ void gemm64_body(const float* __restrict__ A,
                                            const float* __restrict__ W,
                                            float* __restrict__ C,
                                            const int K, const int ks) {
    extern __shared__ unsigned long long smu[];
    unsigned long long* As = smu;               // [kk][34 ull]
    unsigned long long* Wd = smu + AS64_ULL;    // [kk][130 ull]
    float*  asf = (float*)As;                   // idx kk*68 + b
    float2* wdf = (float2*)Wd;                  // idx kk*130 + r
    const int t = threadIdx.x;
    const int r0 = blockIdx.x * 128;
    const int tb = t & 15, tc = t >> 4;

    // issue ALL global loads first (12 LDG.128 in flight per thread)
    float4 pa[4], pw[8];
#pragma unroll
    for (int j = 0; j < 4; ++j) {
        int lin = (t + j * 256) * 4;
        int bb = lin >> 6, kk = lin & 63;
        pa[j] = *(const float4*)(A + (size_t)bb * K + ks + kk);
    }
#pragma unroll
    for (int j = 0; j < 8; ++j) {
        int lin = (t + j * 256) * 4;
        int rr = lin >> 6, kk = lin & 63;
        pw[j] = *(const float4*)(W + (size_t)(r0 + rr) * K + ks + kk);
    }
    // stage
#pragma unroll
    for (int j = 0; j < 4; ++j) {
        int lin = (t + j * 256) * 4;
        int bb = lin >> 6, kk = lin & 63;
        asf[(kk + 0) * 68 + bb] = pa[j].x; asf[(kk + 1) * 68 + bb] = pa[j].y;
        asf[(kk + 2) * 68 + bb] = pa[j].z; asf[(kk + 3) * 68 + bb] = pa[j].w;
    }
#pragma unroll
    for (int j = 0; j < 8; ++j) {
        int lin = (t + j * 256) * 4;
        int rr = lin >> 6, kk = lin & 63;
        wdf[(kk + 0) * 130 + rr] = make_float2(pw[j].x, pw[j].x);
        wdf[(kk + 1) * 130 + rr] = make_float2(pw[j].y, pw[j].y);
        wdf[(kk + 2) * 130 + rr] = make_float2(pw[j].z, pw[j].z);
        wdf[(kk + 3) * 130 + rr] = make_float2(pw[j].w, pw[j].w);
    }
    __syncthreads();

    unsigned long long acc[2][8] = {};
#pragma unroll 4
    for (int kk = 0; kk < 64; ++kk) {
        ulonglong2 av = *(const ulonglong2*)&As[kk * 34 + tb * 2];
#pragma unroll
        for (int j2 = 0; j2 < 4; ++j2) {
            ulonglong2 wv = *(const ulonglong2*)&Wd[kk * 130 + tc * 8 + j2 * 2];
            ffma2(acc[0][j2 * 2 + 0], av.x, wv.x);
            ffma2(acc[1][j2 * 2 + 0], av.y, wv.x);
            ffma2(acc[0][j2 * 2 + 1], av.x, wv.y);
            ffma2(acc[1][j2 * 2 + 1], av.y, wv.y);
        }
    }
#pragma unroll
    for (int p = 0; p < 2; ++p)
#pragma unroll
        for (int j = 0; j < 8; ++j) {
            int r = r0 + tc * 8 + j;
            float lo = __uint_as_float((unsigned)(acc[p][j] & 0xffffffffULL));
            float hi = __uint_as_float((unsigned)(acc[p][j] >> 32));
            int b = tb * 4 + 2 * p;
            C[(size_t)b * 1536 + r] = lo;
            C[(size_t)(b + 1) * 1536 + r] = hi;
        }
}

// gate GEMMs, k-split chunk 64: y selects gx/gh, z selects chunk
__global__ __launch_bounds__(256) void k_gates(const float* A0, const float* W0, int K0,
                                               const float* A1, const float* W1, int K1) {
    const int z = blockIdx.z;
    if (blockIdx.y == 0) {
        if (z * 64 >= K0) return;
        gemm64_body(A0, W0, g_gxp + (size_t)z * 64 * 1536, K0, z * 64);
    } else {
        if (z * 64 >= K1) return;
        gemm64_body(A1, W1, g_ghp + (size_t)z * 64 * 1536, K1, z * 64);
    }
}

// =====================================================================
// GRU pointwise + partial reduction + biases (+bf16 of h1 into x1)
// =====================================================================
__global__ __launch_bounds__(512) void k_gru(int nzx, int nzh, int wr_x1,
                                             const float* __restrict__ bih,
                                             const float* __restrict__ bhh,
                                             const float* __restrict__ hprev,
                                             float* __restrict__ hnew) {
    const int b = blockIdx.x, j = threadIdx.x;
    float xr = bih[j], xz = bih[512 + j], xn = bih[1024 + j];
    for (int z = 0; z < nzx; ++z) {
        const float* p = g_gxp + ((size_t)z * 64 + b) * 1536;
        xr += p[j]; xz += p[512 + j]; xn += p[1024 + j];
    }
    float hr = bhh[j], hz = bhh[512 + j], hn = bhh[1024 + j];
    for (int z = 0; z < nzh; ++z) {
        const float* p = g_ghp + ((size_t)z * 64 + b) * 1536;
        hr += p[j]; hz += p[512 + j]; hn += p[1024 + j];
    }
    float h = hprev[(size_t)b * 512 + j];
    float r = 1.f / (1.f + __expf(-(xr + hr)));
    float z_ = 1.f / (1.f + __expf(-(xz + hz)));
    float n = tanhf(xn + r * hn);
    float hv = (1.f - z_) * n + z_ * h;
    hnew[(size_t)b * 512 + j] = hv;
    if (wr_x1)
        ((__nv_bfloat16*)g_x1h4)[b * 1024 + j] = __float2bfloat16(hv);
}

// =====================================================================
// Output projection: bf16 mma.sync, k-permuted fragments, 128-col tiles
// (grid 393 -> balanced), 3 CTAs/SM, depth-2 W prefetch.
// Warp owns 16 cols (nf=2). Epilogue fuses per-row (max,sumexp) partials.
// =====================================================================
__device__ __forceinline__ void olmerge(float& m, float& s, float v) {
    float nm = fmaxf(m, v);
    s = s * __expf(m - nm) + __expf(v - nm);
    m = nm;
}

__global__ __launch_bounds__(256, 3) void k_proj(const float* __restrict__ W,
                                                 const float* __restrict__ bias,
                                                 float* __restrict__ out) {
    __shared__ uint4 sA[64 * 17];          // A bf16 [row][128-k chunk], pad 17
    __shared__ float2 sRed[64 * 8];        // per-row per-warp (max,sum)
    const int t = threadIdx.x, w = t >> 5, lane = t & 31;
    const int r0 = blockIdx.x * 128 + w * 16;
    const int qr = lane >> 2, qk = lane & 3;

    float acc[4][2][4];
#pragma unroll
    for (int a = 0; a < 4; ++a)
#pragma unroll
        for (int c = 0; c < 2; ++c)
#pragma unroll
            for (int d = 0; d < 4; ++d) acc[a][c][d] = 0.f;

    float4 wbuf[2][2];
    auto ldW = [&](int step, float4* dst) {
        const int koff = step * 16 + 4 * qk;
#pragma unroll
        for (int nf = 0; nf < 2; ++nf) {
            int r = r0 + nf * 8 + qr;
            dst[nf] = make_float4(0.f, 0.f, 0.f, 0.f);
            if (r < V_) dst[nf] = *(const float4*)(W + (size_t)r * 1024 + koff);
        }
    };

    ldW(0, wbuf[0]);
    ldW(1, wbuf[1]);
    for (int step = 0; step < 64; ++step) {
        const int s = step & 7;
        if (s == 0) {   // stage A chunk [64 rows][128 k] as bf16
            const int kc8 = (step >> 3) << 4;
            __syncthreads();
#pragma unroll
            for (int j = 0; j < 4; ++j) {
                int idx = t + j * 256;
                int row = idx >> 4, c8 = idx & 15;
                sA[row * 17 + c8] = g_x1h4[row * 128 + kc8 + c8];
            }
            __syncthreads();
        }
        // consume current, then reload slot with step+2 (depth-2 pipeline)
        unsigned b0[2], b1[2];
#pragma unroll
        for (int nf = 0; nf < 2; ++nf) {
            float4 wr = wbuf[step & 1][nf];
            asm("cvt.rn.bf16x2.f32 %0, %1, %2;" : "=r"(b0[nf]) : "f"(wr.y), "f"(wr.x));
            asm("cvt.rn.bf16x2.f32 %0, %1, %2;" : "=r"(b1[nf]) : "f"(wr.w), "f"(wr.z));
        }
        if (step < 62) ldW(step + 2, wbuf[step & 1]);
#pragma unroll
        for (int mf = 0; mf < 4; ++mf) {
            const char* base = (const char*)sA + s * 32 + qk * 8;
            uint2 alo = *(const uint2*)(base + (mf * 16 + qr) * 272);
            uint2 ahi = *(const uint2*)(base + (mf * 16 + qr + 8) * 272);
#pragma unroll
            for (int nf = 0; nf < 2; ++nf) {
                asm volatile(
                    "mma.sync.aligned.m16n8k16.row.col.f32.bf16.bf16.f32 "
                    "{%0,%1,%2,%3}, {%4,%5,%6,%7}, {%8,%9}, {%0,%1,%2,%3};"
                    : "+f"(acc[mf][nf][0]), "+f"(acc[mf][nf][1]),
                      "+f"(acc[mf][nf][2]), "+f"(acc[mf][nf][3])
                    : "r"(alo.x), "r"(ahi.x), "r"(alo.y), "r"(ahi.y),
                      "r"(b0[nf]), "r"(b1[nf]));
            }
        }
    }

    // ---- epilogue: bias + store + fused per-row (max, sumexp) partials ----
    float rm[4][2], rs[4][2];
#pragma unroll
    for (int mf = 0; mf < 4; ++mf) { rm[mf][0] = rm[mf][1] = -3.0e38f;
                                     rs[mf][0] = rs[mf][1] = 0.f; }
#pragma unroll
    for (int mf = 0; mf < 4; ++mf) {
        const int m0 = mf * 16 + qr;
#pragma unroll
        for (int nf = 0; nf < 2; ++nf) {
            int rr = r0 + nf * 8 + 2 * qk;
            if (rr < V_) {
                float bv = bias[rr];
                float l0 = acc[mf][nf][0] + bv, l2 = acc[mf][nf][2] + bv;
                out[(size_t)m0 * V_ + rr] = l0;
                out[(size_t)(m0 + 8) * V_ + rr] = l2;
                olmerge(rm[mf][0], rs[mf][0], l0);
                olmerge(rm[mf][1], rs[mf][1], l2);
            }
            if (rr + 1 < V_) {
                float bv = bias[rr + 1];
                float l1 = acc[mf][nf][1] + bv, l3 = acc[mf][nf][3] + bv;
                out[(size_t)m0 * V_ + rr + 1] = l1;
                out[(size_t)(m0 + 8) * V_ + rr + 1] = l3;
                olmerge(rm[mf][0], rs[mf][0], l1);
                olmerge(rm[mf][1], rs[mf][1], l3);
            }
        }
    }
    // reduce across the 4 qk threads of each quad
#pragma unroll
    for (int mf = 0; mf < 4; ++mf)
#pragma unroll
        for (int hf = 0; hf < 2; ++hf) {
#pragma unroll
            for (int o = 1; o <= 2; o <<= 1) {
                float om = __shfl_xor_sync(0xffffffffu, rm[mf][hf], o);
                float os = __shfl_xor_sync(0xffffffffu, rs[mf][hf], o);
                float nm = fmaxf(rm[mf][hf], om);
                rs[mf][hf] = rs[mf][hf] * __expf(rm[mf][hf] - nm) + os * __expf(om - nm);
                rm[mf][hf] = nm;
            }
            if (qk == 0)
                sRed[(mf * 16 + qr + 8 * hf) * 8 + w] = make_float2(rm[mf][hf], rs[mf][hf]);
        }
    __syncthreads();
    if (t < 64) {
        float m = -3.0e38f, s = 0.f;
#pragma unroll
        for (int i = 0; i < 8; ++i) {
            float2 p = sRed[t * 8 + i];
            float nm = fmaxf(m, p.x);
            s = s * __expf(m - nm) + p.y * __expf(p.x - nm);
            m = nm;
        }
        g_pm[(size_t)blockIdx.x * 64 + t] = make_float2(m, s);
    }
}

// =====================================================================
// combine per-CTA lsm partials -> per-row lse (393 partials per row)
// =====================================================================
__global__ __launch_bounds__(512) void k_lsm_comb() {
    const int b = blockIdx.x, t = threadIdx.x;
    __shared__ float redm[16], reds[16];
    float m = -3.0e38f, s = 0.f;
    if (t < NPROJ) {
        float2 p = g_pm[(size_t)t * 64 + b];
        m = p.x; s = p.y;
    }
#pragma unroll
    for (int o = 16; o; o >>= 1) {
        float om = __shfl_xor_sync(0xffffffffu, m, o);
        float os = __shfl_xor_sync(0xffffffffu, s, o);
        float nm = fmaxf(m, om);
        s = s * __expf(m - nm) + os * __expf(om - nm);
        m = nm;
    }
    if ((t & 31) == 0) { redm[t >> 5] = m; reds[t >> 5] = s; }
    __syncthreads();
    if (t == 0) {
        float mm = redm[0], ss = reds[0];
        for (int i = 1; i < 16; ++i) {
            float nm = fmaxf(mm, redm[i]);
            ss = ss * __expf(mm - nm) + reds[i] * __expf(redm[i] - nm);
            mm = nm;
        }
        g_lsmv[b] = mm + logf(ss);
    }
}

// =====================================================================
// subtract lse in place
// =====================================================================
#define LSM_CHUNK 6284   // ceil(50257/8)
__global__ __launch_bounds__(512) void k_lsm2(float* __restrict__ out) {
    const int c = blockIdx.x, b = blockIdx.y, t = threadIdx.x;
    float* row = out + (size_t)b * V_;
    const float lse = g_lsmv[b];
    const int i0 = c * LSM_CHUNK, i1 = min(i0 + LSM_CHUNK, V_);
    for (int i = i0 + t; i < i1; i += 512) row[i] -= lse;
}

// =====================================================================
extern "C" void kernel_launch(void* const* d_in, const int* in_sizes, int n_in,
                              void* d_out, int out_size) {
    const int* ids = (const int*)d_in[0];
    const float* hidden = (const float*)d_in[1];
    const float* baw = (const float*)d_in[2];
    const float* enc = (const float*)d_in[3];
    int o = (n_in >= 5 && in_sizes[4] == 1) ? 1 : 0;
    const float* emb    = (const float*)d_in[4 + o];
    const float* attn_W = (const float*)d_in[5 + o];
    // attn_b (d_in[6+o]) is softmax-shift invariant — unused
    const float* W_ih0  = (const float*)d_in[7 + o];
    const float* W_hh0  = (const float*)d_in[8 + o];
    const float* b_ih0  = (const float*)d_in[9 + o];
    const float* b_hh0  = (const float*)d_in[10 + o];
    const float* W_ih1  = (const float*)d_in[11 + o];
    const float* W_hh1  = (const float*)d_in[12 + o];
    const float* b_ih1  = (const float*)d_in[13 + o];
    const float* b_hh1  = (const float*)d_in[14 + o];
    const float* out_W  = (const float*)d_in[15 + o];
    const float* out_b  = (const float*)d_in[16 + o];
    float* out = (float*)d_out;

    float* p_x0;
    cudaGetSymbolAddress((void**)&p_x0, g_x0);

    const int attn_smem = (64 * 512 + 512 + 64) * 4;  // 133376 B
    cudaFuncSetAttribute(k_attn, cudaFuncAttributeMaxDynamicSharedMemorySize, attn_smem);
    cudaFuncSetAttribute(k_gates, cudaFuncAttributeMaxDynamicSharedMemorySize, GEMM_SMEM_BYTES);

    // 1. u = h1 @ attn_W (8x8 partials)
    k_u_part<<<dim3(8, 8), 256>>>(hidden, attn_W);
    // 2. per-block attention
    k_attn<<<2048, 512, attn_smem>>>(enc, out);
    // 3. context reduce + embedding gather + concat buffers
    k_ctx<<<64, 512>>>(baw, emb, ids, out);
    // 4. GRU layer 0 gates (k-split 64, single-shot), pointwise+reduce
    k_gates<<<dim3(12, 2, 16), 256, GEMM_SMEM_BYTES>>>(p_x0, W_ih0, 1024,
                                                       hidden, W_hh0, 512);
    k_gru<<<64, 512>>>(16, 8, 0, b_ih0, b_hh0, hidden, out + OFF_NH);
    // 5. GRU layer 1 gates, pointwise+reduce (writes x1 bf16)
    k_gates<<<dim3(12, 2, 8), 256, GEMM_SMEM_BYTES>>>(out + OFF_NH, W_ih1, 512,
                                                      hidden + 64 * 512, W_hh1, 512);
    k_gru<<<64, 512>>>(8, 8, 1, b_ih1, b_hh1, hidden + 64 * 512,
                       out + OFF_NH + 64 * 512);
    // 6. output projection (fused lsm partials), 128-col balanced tiles
    k_proj<<<NPROJ, 256>>>(out_W, out_b, out);
    // 7. combine lse + subtract
    k_lsm_comb<<<64, 512>>>();
    k_lsm2<<<dim3(8, 64), 512>>>(out);
}

// round 11
// speedup vs baseline: 1.2328x; 1.2328x over previous
#include <cuda_runtime.h>
#include <cuda_bf16.h>
#include <cstdint>

#define B_ 64
#define H_ 512
#define V_ 50257
#define NPROJ 393            // ceil(V_/128)

// ---- scratch (__device__ globals; no allocation allowed) ----
__device__ float g_upart[8 * 64 * 512];      // partial u = h1 @ attn_W
__device__ float g_bctx[64 * 32 * 512];      // block contexts
__device__ float g_x0[64 * 1024];            // [embedded | context] fp32 (layer-0 input)
__device__ uint4 g_x1h4[8192];               // x1 bf16  [64][1024]
__device__ float g_gxp[16 * 64 * 1536];      // gx partials (k-split)
__device__ float g_ghp[8 * 64 * 1536];       // gh partials (k-split)
__device__ float2 g_pm[NPROJ * 64];          // per-CTA per-row (max, sumexp)
__device__ float g_lsmv[64];                 // per-row lse

// ---- output layout: log_probs, new_hidden[2,B,H], context[B,H], attn_w[B,32,64]
#define OFF_NH   ((size_t)B_ * V_)
#define OFF_CTX  (OFF_NH + (size_t)2 * B_ * H_)
#define OFF_ATTN (OFF_CTX + (size_t)B_ * H_)

// =====================================================================
// u partials: u[b,h] = sum_g h1[b,g] * attn_W[g,h]
// =====================================================================
__global__ __launch_bounds__(256) void k_u_part(const float* __restrict__ hidden,
                                                const float* __restrict__ attn_W) {
    __shared__ float Hs[64 * 65];
    __shared__ float Ws[64 * 65];
    const int t = threadIdx.x;
    const int h0 = blockIdx.x * 64, g0 = blockIdx.y * 64;
    const float* h1 = hidden + 64 * 512;  // hidden[-1]
#pragma unroll
    for (int j = 0; j < 4; ++j) {
        int lin = (t + j * 256) * 4;
        int bb = lin >> 6, kk = lin & 63;
        float4 v = *(const float4*)(h1 + (size_t)bb * 512 + g0 + kk);
        Hs[bb * 65 + kk + 0] = v.x; Hs[bb * 65 + kk + 1] = v.y;
        Hs[bb * 65 + kk + 2] = v.z; Hs[bb * 65 + kk + 3] = v.w;
    }
#pragma unroll
    for (int j = 0; j < 4; ++j) {
        int lin = (t + j * 256) * 4;
        int kk = lin >> 6, hh = lin & 63;
        float4 v = *(const float4*)(attn_W + (size_t)(g0 + kk) * 512 + h0 + hh);
        Ws[(hh + 0) * 65 + kk] = v.x; Ws[(hh + 1) * 65 + kk] = v.y;
        Ws[(hh + 2) * 65 + kk] = v.z; Ws[(hh + 3) * 65 + kk] = v.w;
    }
    __syncthreads();
    const int tb = t & 15, tc = t >> 4;
    float acc[4][4] = {};
#pragma unroll 8
    for (int kk = 0; kk < 64; ++kk) {
        float a0 = Hs[(tb * 4 + 0) * 65 + kk];
        float a1 = Hs[(tb * 4 + 1) * 65 + kk];
        float a2 = Hs[(tb * 4 + 2) * 65 + kk];
        float a3 = Hs[(tb * 4 + 3) * 65 + kk];
#pragma unroll
        for (int j = 0; j < 4; ++j) {
            float wv = Ws[(tc * 4 + j) * 65 + kk];
            acc[0][j] += a0 * wv; acc[1][j] += a1 * wv;
            acc[2][j] += a2 * wv; acc[3][j] += a3 * wv;
        }
    }
#pragma unroll
    for (int i = 0; i < 4; ++i)
#pragma unroll
        for (int j = 0; j < 4; ++j)
            g_upart[((size_t)blockIdx.y * 64 + tb * 4 + i) * 512 + h0 + tc * 4 + j] = acc[i][j];
}

// =====================================================================
// Block attention: one CTA per (b, n); tile cached in smem for 2nd pass.
// =====================================================================
__global__ __launch_bounds__(512) void k_attn(const float* __restrict__ enc,
                                              float* __restrict__ out) {
    extern __shared__ float sm[];
    float* tile = sm;                       // 64*512
    float* u_s  = sm + 64 * 512;            // 512
    float* sc   = sm + 64 * 512 + 512;      // 64
    const int t = threadIdx.x, w = t >> 5, lane = t & 31;
    const int bn = blockIdx.x;
    const int b = bn >> 5;

    {   float s = 0.f;
#pragma unroll
        for (int p = 0; p < 8; ++p) s += g_upart[((size_t)p * 64 + b) * 512 + t];
        u_s[t] = s;
    }
    __syncthreads();

    float uu[4][4];
#pragma unroll
    for (int j = 0; j < 4; ++j) {
        float4 q = *(const float4*)&u_s[(lane + 32 * j) * 4];
        uu[j][0] = q.x; uu[j][1] = q.y; uu[j][2] = q.z; uu[j][3] = q.w;
    }
    const float4* eo4 = (const float4*)(enc + (size_t)bn * (64 * 512));
    float4* tile4 = (float4*)tile;
#pragma unroll
    for (int i = 0; i < 4; ++i) {
        const int l = w * 4 + i;
        float acc = 0.f;
#pragma unroll
        for (int j = 0; j < 4; ++j) {
            float4 v = eo4[l * 128 + lane + 32 * j];
            tile4[l * 128 + lane + 32 * j] = v;
            acc += v.x * uu[j][0] + v.y * uu[j][1] + v.z * uu[j][2] + v.w * uu[j][3];
        }
#pragma unroll
        for (int o = 16; o; o >>= 1) acc += __shfl_xor_sync(0xffffffffu, acc, o);
        if (lane == 0) sc[l] = acc;
    }
    __syncthreads();

    if (w == 0) {
        float s0 = sc[lane], s1 = sc[lane + 32];
        float m = fmaxf(s0, s1);
#pragma unroll
        for (int o = 16; o; o >>= 1) m = fmaxf(m, __shfl_xor_sync(0xffffffffu, m, o));
        float e0 = __expf(s0 - m), e1 = __expf(s1 - m);
        float s = e0 + e1;
#pragma unroll
        for (int o = 16; o; o >>= 1) s += __shfl_xor_sync(0xffffffffu, s, o);
        float inv = 1.f / s;
        float w0 = e0 * inv, w1 = e1 * inv;
        sc[lane] = w0; sc[lane + 32] = w1;
        out[OFF_ATTN + (size_t)bn * 64 + lane] = w0;
        out[OFF_ATTN + (size_t)bn * 64 + lane + 32] = w1;
    }
    __syncthreads();

    float acc = 0.f;
#pragma unroll 8
    for (int l = 0; l < 64; ++l) acc += sc[l] * tile[l * 512 + t];
    g_bctx[(size_t)bn * 512 + t] = acc;
}

// =====================================================================
// context reduce + embedding gather + concat inputs (+bf16 of ctx)
// =====================================================================
__global__ __launch_bounds__(512) void k_ctx(const float* __restrict__ baw,
                                             const float* __restrict__ emb,
                                             const int* __restrict__ ids,
                                             float* __restrict__ out) {
    const int b = blockIdx.x, h = threadIdx.x;
    float acc = 0.f;
#pragma unroll 8
    for (int n = 0; n < 32; ++n)
        acc += baw[b * 32 + n] * g_bctx[((size_t)b * 32 + n) * 512 + h];
    out[OFF_CTX + (size_t)b * 512 + h] = acc;
    g_x0[b * 1024 + 512 + h] = acc;
    ((__nv_bfloat16*)g_x1h4)[b * 1024 + 512 + h] = __float2bfloat16(acc);
    g_x0[b * 1024 + h] = emb[(size_t)ids[b] * 512 + h];
}

// =====================================================================
// FFMA2 GEMM body (gate GEMMs): double-buffered, register prefetch
// (Round-9 version — 24.5us/launch measured)
// =====================================================================
__device__ __forceinline__ void ffma2(unsigned long long& d, unsigned long long a,
                                      unsigned long long b) {
    asm("fma.rn.f32x2 %0, %1, %2, %0;" : "+l"(d) : "l"(a), "l"(b));
}

#define AS_ULL 1088              // 32 * 34
#define WD_ULL 4160              // 32 * 130
#define GEMM_SMEM_BYTES ((2 * AS_ULL + 2 * WD_ULL) * 8)   // 83968

__device__ __forceinline__ void gemm_body(const float* __restrict__ A,
                                          const float* __restrict__ W,
                                          float* __restrict__ C,
                                          const int R, const int K,
                                          const int ks, const int ke, const int ldc) {
    extern __shared__ unsigned long long smu[];
    unsigned long long* As = smu;
    unsigned long long* Wd = smu + 2 * AS_ULL;
    const int t = threadIdx.x;
    const int r0 = blockIdx.x * 128;
    const int tb = t & 15, tc = t >> 4;
    unsigned long long acc[2][8] = {};
    float4 pa[2], pw[4];

    auto ldT = [&](int k0) {
#pragma unroll
        for (int j = 0; j < 2; ++j) {
            int lin = (t + j * 256) * 4;
            int bb = lin >> 5, kk = lin & 31;
            pa[j] = *(const float4*)(A + (size_t)bb * K + k0 + kk);
        }
#pragma unroll
        for (int j = 0; j < 4; ++j) {
            int lin = (t + j * 256) * 4;
            int rr = lin >> 5, kk = lin & 31;
            pw[j] = make_float4(0.f, 0.f, 0.f, 0.f);
            if (r0 + rr < R) pw[j] = *(const float4*)(W + (size_t)(r0 + rr) * K + k0 + kk);
        }
    };
    auto stT = [&](int buf) {
        float*  asf = (float*)(As + buf * AS_ULL);
        float2* wdf = (float2*)(Wd + buf * WD_ULL);
#pragma unroll
        for (int j = 0; j < 2; ++j) {
            int lin = (t + j * 256) * 4;
            int bb = lin >> 5, kk = lin & 31;
            asf[(kk + 0) * 68 + bb] = pa[j].x; asf[(kk + 1) * 68 + bb] = pa[j].y;
            asf[(kk + 2) * 68 + bb] = pa[j].z; asf[(kk + 3) * 68 + bb] = pa[j].w;
        }
#pragma unroll
        for (int j = 0; j < 4; ++j) {
            int lin = (t + j * 256) * 4;
            int rr = lin >> 5, kk = lin & 31;
            wdf[(kk + 0) * 130 + rr] = make_float2(pw[j].x, pw[j].x);
            wdf[(kk + 1) * 130 + rr] = make_float2(pw[j].y, pw[j].y);
            wdf[(kk + 2) * 130 + rr] = make_float2(pw[j].z, pw[j].z);
            wdf[(kk + 3) * 130 + rr] = make_float2(pw[j].w, pw[j].w);
        }
    };

    ldT(ks);
    stT(0);
    __syncthreads();
    int buf = 0;
    for (int k0 = ks; k0 < ke; k0 += 32) {
        const bool more = (k0 + 32) < ke;
        if (more) ldT(k0 + 32);
        const unsigned long long* Ab = As + buf * AS_ULL;
        const unsigned long long* Wb = Wd + buf * WD_ULL;
#pragma unroll 4
        for (int kk = 0; kk < 32; ++kk) {
            ulonglong2 av = *(const ulonglong2*)&Ab[kk * 34 + tb * 2];
#pragma unroll
            for (int j2 = 0; j2 < 4; ++j2) {
                ulonglong2 wv = *(const ulonglong2*)&Wb[kk * 130 + tc * 8 + j2 * 2];
                ffma2(acc[0][j2 * 2 + 0], av.x, wv.x);
                ffma2(acc[1][j2 * 2 + 0], av.y, wv.x);
                ffma2(acc[0][j2 * 2 + 1], av.x, wv.y);
                ffma2(acc[1][j2 * 2 + 1], av.y, wv.y);
            }
        }
        if (more) stT(buf ^ 1);
        __syncthreads();
        buf ^= 1;
    }
#pragma unroll
    for (int p = 0; p < 2; ++p)
#pragma unroll
        for (int j = 0; j < 8; ++j) {
            int r = r0 + tc * 8 + j;
            if (r < R) {
                float lo = __uint_as_float((unsigned)(acc[p][j] & 0xffffffffULL));
                float hi = __uint_as_float((unsigned)(acc[p][j] >> 32));
                int b = tb * 4 + 2 * p;
                C[(size_t)b * ldc + r] = lo;
                C[(size_t)(b + 1) * ldc + r] = hi;
            }
        }
}

// gate GEMMs, k-split chunk 64: y selects gx/gh, z selects chunk
__global__ __launch_bounds__(256) void k_gates(const float* A0, const float* W0, int K0,
                                               const float* A1, const float* W1, int K1) {
    const int z = blockIdx.z;
    if (blockIdx.y == 0) {
        if (z * 64 >= K0) return;
        gemm_body(A0, W0, g_gxp + (size_t)z * 64 * 1536, 1536, K0,
                  z * 64, z * 64 + 64, 1536);
    } else {
        if (z * 64 >= K1) return;
        gemm_body(A1, W1, g_ghp + (size_t)z * 64 * 1536, 1536, K1,
                  z * 64, z * 64 + 64, 1536);
    }
}

// =====================================================================
// GRU pointwise + partial reduction + biases (+bf16 of h1 into x1)
// =====================================================================
__global__ __launch_bounds__(512) void k_gru(int nzx, int nzh, int wr_x1,
                                             const float* __restrict__ bih,
                                             const float* __restrict__ bhh,
                                             const float* __restrict__ hprev,
                                             float* __restrict__ hnew) {
    const int b = blockIdx.x, j = threadIdx.x;
    float xr = bih[j], xz = bih[512 + j], xn = bih[1024 + j];
    for (int z = 0; z < nzx; ++z) {
        const float* p = g_gxp + ((size_t)z * 64 + b) * 1536;
        xr += p[j]; xz += p[512 + j]; xn += p[1024 + j];
    }
    float hr = bhh[j], hz = bhh[512 + j], hn = bhh[1024 + j];
    for (int z = 0; z < nzh; ++z) {
        const float* p = g_ghp + ((size_t)z * 64 + b) * 1536;
        hr += p[j]; hz += p[512 + j]; hn += p[1024 + j];
    }
    float h = hprev[(size_t)b * 512 + j];
    float r = 1.f / (1.f + __expf(-(xr + hr)));
    float z_ = 1.f / (1.f + __expf(-(xz + hz)));
    float n = tanhf(xn + r * hn);
    float hv = (1.f - z_) * n + z_ * h;
    hnew[(size_t)b * 512 + j] = hv;
    if (wr_x1)
        ((__nv_bfloat16*)g_x1h4)[b * 1024 + j] = __float2bfloat16(hv);
}

// =====================================================================
// Output projection: bf16 mma.sync, k-permuted fragments, 128-col tiles
// (grid 393 -> balance 0.89), depth-2 W prefetch, NO forced occupancy
// (launch_bounds(256,2): 128-reg budget, no spills).
// =====================================================================
__device__ __forceinline__ void olmerge(float& m, float& s, float v) {
    float nm = fmaxf(m, v);
    s = s * __expf(m - nm) + __expf(v - nm);
    m = nm;
}

__global__ __launch_bounds__(256, 2) void k_proj(const float* __restrict__ W,
                                                 const float* __restrict__ bias,
                                                 float* __restrict__ out) {
    __shared__ uint4 sA[64 * 17];          // A bf16 [row][128-k chunk], pad 17
    __shared__ float2 sRed[64 * 8];        // per-row per-warp (max,sum)
    const int t = threadIdx.x, w = t >> 5, lane = t & 31;
    const int r0 = blockIdx.x * 128 + w * 16;
    const int qr = lane >> 2, qk = lane & 3;

    float acc[4][2][4];
#pragma unroll
    for (int a = 0; a < 4; ++a)
#pragma unroll
        for (int c = 0; c < 2; ++c)
#pragma unroll
            for (int d = 0; d < 4; ++d) acc[a][c][d] = 0.f;

    float4 wbuf[2][2];
    auto ldW = [&](int step, float4* dst) {
        const int koff = step * 16 + 4 * qk;
#pragma unroll
        for (int nf = 0; nf < 2; ++nf) {
            int r = r0 + nf * 8 + qr;
            dst[nf] = make_float4(0.f, 0.f, 0.f, 0.f);
            if (r < V_) dst[nf] = *(const float4*)(W + (size_t)r * 1024 + koff);
        }
    };

    ldW(0, wbuf[0]);
    ldW(1, wbuf[1]);
    for (int step = 0; step < 64; ++step) {
        const int s = step & 7;
        if (s == 0) {   // stage A chunk [64 rows][128 k] as bf16
            const int kc8 = (step >> 3) << 4;
            __syncthreads();
#pragma unroll
            for (int j = 0; j < 4; ++j) {
                int idx = t + j * 256;
                int row = idx >> 4, c8 = idx & 15;
                sA[row * 17 + c8] = g_x1h4[row * 128 + kc8 + c8];
            }
            __syncthreads();
        }
        // consume current slot, reload it with step+2 (depth-2 pipeline)
        unsigned b0[2], b1[2];
#pragma unroll
        for (int nf = 0; nf < 2; ++nf) {
            float4 wr = wbuf[step & 1][nf];
            asm("cvt.rn.bf16x2.f32 %0, %1, %2;" : "=r"(b0[nf]) : "f"(wr.y), "f"(wr.x));
            asm("cvt.rn.bf16x2.f32 %0, %1, %2;" : "=r"(b1[nf]) : "f"(wr.w), "f"(wr.z));
        }
        if (step < 62) ldW(step + 2, wbuf[step & 1]);
#pragma unroll
        for (int mf = 0; mf < 4; ++mf) {
            const char* base = (const char*)sA + s * 32 + qk * 8;
            uint2 alo = *(const uint2*)(base + (mf * 16 + qr) * 272);
            uint2 ahi = *(const uint2*)(base + (mf * 16 + qr + 8) * 272);
#pragma unroll
            for (int nf = 0; nf < 2; ++nf) {
                asm volatile(
                    "mma.sync.aligned.m16n8k16.row.col.f32.bf16.bf16.f32 "
                    "{%0,%1,%2,%3}, {%4,%5,%6,%7}, {%8,%9}, {%0,%1,%2,%3};"
                    : "+f"(acc[mf][nf][0]), "+f"(acc[mf][nf][1]),
                      "+f"(acc[mf][nf][2]), "+f"(acc[mf][nf][3])
                    : "r"(alo.x), "r"(ahi.x), "r"(alo.y), "r"(ahi.y),
                      "r"(b0[nf]), "r"(b1[nf]));
            }
        }
    }

    // ---- epilogue: bias + store + fused per-row (max, sumexp) partials ----
    float rm[4][2], rs[4][2];
#pragma unroll
    for (int mf = 0; mf < 4; ++mf) { rm[mf][0] = rm[mf][1] = -3.0e38f;
                                     rs[mf][0] = rs[mf][1] = 0.f; }
#pragma unroll
    for (int mf = 0; mf < 4; ++mf) {
        const int m0 = mf * 16 + qr;
#pragma unroll
        for (int nf = 0; nf < 2; ++nf) {
            int rr = r0 + nf * 8 + 2 * qk;
            if (rr < V_) {
                float bv = bias[rr];
                float l0 = acc[mf][nf][0] + bv, l2 = acc[mf][nf][2] + bv;
                out[(size_t)m0 * V_ + rr] = l0;
                out[(size_t)(m0 + 8) * V_ + rr] = l2;
                olmerge(rm[mf][0], rs[mf][0], l0);
                olmerge(rm[mf][1], rs[mf][1], l2);
            }
            if (rr + 1 < V_) {
                float bv = bias[rr + 1];
                float l1 = acc[mf][nf][1] + bv, l3 = acc[mf][nf][3] + bv;
                out[(size_t)m0 * V_ + rr + 1] = l1;
                out[(size_t)(m0 + 8) * V_ + rr + 1] = l3;
                olmerge(rm[mf][0], rs[mf][0], l1);
                olmerge(rm[mf][1], rs[mf][1], l3);
            }
        }
    }
    // reduce across the 4 qk threads of each quad
#pragma unroll
    for (int mf = 0; mf < 4; ++mf)
#pragma unroll
        for (int hf = 0; hf < 2; ++hf) {
#pragma unroll
            for (int o = 1; o <= 2; o <<= 1) {
                float om = __shfl_xor_sync(0xffffffffu, rm[mf][hf], o);
                float os = __shfl_xor_sync(0xffffffffu, rs[mf][hf], o);
                float nm = fmaxf(rm[mf][hf], om);
                rs[mf][hf] = rs[mf][hf] * __expf(rm[mf][hf] - nm) + os * __expf(om - nm);
                rm[mf][hf] = nm;
            }
            if (qk == 0)
                sRed[(mf * 16 + qr + 8 * hf) * 8 + w] = make_float2(rm[mf][hf], rs[mf][hf]);
        }
    __syncthreads();
    if (t < 64) {
        float m = -3.0e38f, s = 0.f;
#pragma unroll
        for (int i = 0; i < 8; ++i) {
            float2 p = sRed[t * 8 + i];
            float nm = fmaxf(m, p.x);
            s = s * __expf(m - nm) + p.y * __expf(p.x - nm);
            m = nm;
        }
        g_pm[(size_t)blockIdx.x * 64 + t] = make_float2(m, s);
    }
}

// =====================================================================
// combine per-CTA lsm partials -> per-row lse (393 partials per row)
// =====================================================================
__global__ __launch_bounds__(512) void k_lsm_comb() {
    const int b = blockIdx.x, t = threadIdx.x;
    __shared__ float redm[16], reds[16];
    float m = -3.0e38f, s = 0.f;
    if (t < NPROJ) {
        float2 p = g_pm[(size_t)t * 64 + b];
        m = p.x; s = p.y;
    }
#pragma unroll
    for (int o = 16; o; o >>= 1) {
        float om = __shfl_xor_sync(0xffffffffu, m, o);
        float os = __shfl_xor_sync(0xffffffffu, s, o);
        float nm = fmaxf(m, om);
        s = s * __expf(m - nm) + os * __expf(om - nm);
        m = nm;
    }
    if ((t & 31) == 0) { redm[t >> 5] = m; reds[t >> 5] = s; }
    __syncthreads();
    if (t == 0) {
        float mm = redm[0], ss = reds[0];
        for (int i = 1; i < 16; ++i) {
            float nm = fmaxf(mm, redm[i]);
            ss = ss * __expf(mm - nm) + reds[i] * __expf(redm[i] - nm);
            mm = nm;
        }
        g_lsmv[b] = mm + logf(ss);
    }
}

// =====================================================================
// subtract lse in place
// =====================================================================
#define LSM_CHUNK 6284   // ceil(50257/8)
__global__ __launch_bounds__(512) void k_lsm2(float* __restrict__ out) {
    const int c = blockIdx.x, b = blockIdx.y, t = threadIdx.x;
    float* row = out + (size_t)b * V_;
    const float lse = g_lsmv[b];
    const int i0 = c * LSM_CHUNK, i1 = min(i0 + LSM_CHUNK, V_);
    for (int i = i0 + t; i < i1; i += 512) row[i] -= lse;
}

// =====================================================================
extern "C" void kernel_launch(void* const* d_in, const int* in_sizes, int n_in,
                              void* d_out, int out_size) {
    const int* ids = (const int*)d_in[0];
    const float* hidden = (const float*)d_in[1];
    const float* baw = (const float*)d_in[2];
    const float* enc = (const float*)d_in[3];
    int o = (n_in >= 5 && in_sizes[4] == 1) ? 1 : 0;
    const float* emb    = (const float*)d_in[4 + o];
    const float* attn_W = (const float*)d_in[5 + o];
    // attn_b (d_in[6+o]) is softmax-shift invariant — unused
    const float* W_ih0  = (const float*)d_in[7 + o];
    const float* W_hh0  = (const float*)d_in[8 + o];
    const float* b_ih0  = (const float*)d_in[9 + o];
    const float* b_hh0  = (const float*)d_in[10 + o];
    const float* W_ih1  = (const float*)d_in[11 + o];
    const float* W_hh1  = (const float*)d_in[12 + o];
    const float* b_ih1  = (const float*)d_in[13 + o];
    const float* b_hh1  = (const float*)d_in[14 + o];
    const float* out_W  = (const float*)d_in[15 + o];
    const float* out_b  = (const float*)d_in[16 + o];
    float* out = (float*)d_out;

    float* p_x0;
    cudaGetSymbolAddress((void**)&p_x0, g_x0);

    const int attn_smem = (64 * 512 + 512 + 64) * 4;  // 133376 B
    cudaFuncSetAttribute(k_attn, cudaFuncAttributeMaxDynamicSharedMemorySize, attn_smem);
    cudaFuncSetAttribute(k_gates, cudaFuncAttributeMaxDynamicSharedMemorySize, GEMM_SMEM_BYTES);

    // 1. u = h1 @ attn_W (8x8 partials)
    k_u_part<<<dim3(8, 8), 256>>>(hidden, attn_W);
    // 2. per-block attention
    k_attn<<<2048, 512, attn_smem>>>(enc, out);
    // 3. context reduce + embedding gather + concat buffers
    k_ctx<<<64, 512>>>(baw, emb, ids, out);
    // 4. GRU layer 0 gates (k-split 64), pointwise+reduce
    k_gates<<<dim3(12, 2, 16), 256, GEMM_SMEM_BYTES>>>(p_x0, W_ih0, 1024,
                                                       hidden, W_hh0, 512);
    k_gru<<<64, 512>>>(16, 8, 0, b_ih0, b_hh0, hidden, out + OFF_NH);
    // 5. GRU layer 1 gates, pointwise+reduce (writes x1 bf16)
    k_gates<<<dim3(12, 2, 8), 256, GEMM_SMEM_BYTES>>>(out + OFF_NH, W_ih1, 512,
                                                      hidden + 64 * 512, W_hh1, 512);
    k_gru<<<64, 512>>>(8, 8, 1, b_ih1, b_hh1, hidden + 64 * 512,
                       out + OFF_NH + 64 * 512);
    // 6. output projection (fused lsm partials), 128-col balanced tiles
    k_proj<<<NPROJ, 256>>>(out_W, out_b, out);
    // 7. combine lse + subtract
    k_lsm_comb<<<64, 512>>>();
    k_lsm2<<<dim3(8, 64), 512>>>(out);
}

// round 12
// speedup vs baseline: 1.7337x; 1.4063x over previous
#include <cuda_runtime.h>
#include <cuda_bf16.h>
#include <cstdint>

#define B_ 64
#define H_ 512
#define V_ 50257
#define NPROJ 197            // ceil(V_/256)

// ---- scratch (__device__ globals; no allocation allowed) ----
__device__ float g_upart[8 * 64 * 512];      // partial u = h1 @ attn_W
__device__ float g_bctx[64 * 32 * 512];      // block contexts
__device__ float g_x0[64 * 1024];            // [embedded | context] fp32 (layer-0 input)
__device__ uint4 g_x1h4[8192];               // x1 bf16  [64][1024]
__device__ float g_gxp[16 * 64 * 1536];      // gx partials (k-split)
__device__ float g_ghp[8 * 64 * 1536];       // gh partials (k-split)
__device__ float2 g_pm[NPROJ * 64];          // per-CTA per-row (max, sumexp)
__device__ float g_lsmv[64];                 // per-row lse

// ---- output layout: log_probs, new_hidden[2,B,H], context[B,H], attn_w[B,32,64]
#define OFF_NH   ((size_t)B_ * V_)
#define OFF_CTX  (OFF_NH + (size_t)2 * B_ * H_)
#define OFF_ATTN (OFF_CTX + (size_t)B_ * H_)

// =====================================================================
// u partials: u[b,h] = sum_g h1[b,g] * attn_W[g,h]
// =====================================================================
__global__ __launch_bounds__(256) void k_u_part(const float* __restrict__ hidden,
                                                const float* __restrict__ attn_W) {
    __shared__ float Hs[64 * 65];
    __shared__ float Ws[64 * 65];
    const int t = threadIdx.x;
    const int h0 = blockIdx.x * 64, g0 = blockIdx.y * 64;
    const float* h1 = hidden + 64 * 512;  // hidden[-1]
#pragma unroll
    for (int j = 0; j < 4; ++j) {
        int lin = (t + j * 256) * 4;
        int bb = lin >> 6, kk = lin & 63;
        float4 v = *(const float4*)(h1 + (size_t)bb * 512 + g0 + kk);
        Hs[bb * 65 + kk + 0] = v.x; Hs[bb * 65 + kk + 1] = v.y;
        Hs[bb * 65 + kk + 2] = v.z; Hs[bb * 65 + kk + 3] = v.w;
    }
#pragma unroll
    for (int j = 0; j < 4; ++j) {
        int lin = (t + j * 256) * 4;
        int kk = lin >> 6, hh = lin & 63;
        float4 v = *(const float4*)(attn_W + (size_t)(g0 + kk) * 512 + h0 + hh);
        Ws[(hh + 0) * 65 + kk] = v.x; Ws[(hh + 1) * 65 + kk] = v.y;
        Ws[(hh + 2) * 65 + kk] = v.z; Ws[(hh + 3) * 65 + kk] = v.w;
    }
    __syncthreads();
    const int tb = t & 15, tc = t >> 4;
    float acc[4][4] = {};
#pragma unroll 8
    for (int kk = 0; kk < 64; ++kk) {
        float a0 = Hs[(tb * 4 + 0) * 65 + kk];
        float a1 = Hs[(tb * 4 + 1) * 65 + kk];
        float a2 = Hs[(tb * 4 + 2) * 65 + kk];
        float a3 = Hs[(tb * 4 + 3) * 65 + kk];
#pragma unroll
        for (int j = 0; j < 4; ++j) {
            float wv = Ws[(tc * 4 + j) * 65 + kk];
            acc[0][j] += a0 * wv; acc[1][j] += a1 * wv;
            acc[2][j] += a2 * wv; acc[3][j] += a3 * wv;
        }
    }
#pragma unroll
    for (int i = 0; i < 4; ++i)
#pragma unroll
        for (int j = 0; j < 4; ++j)
            g_upart[((size_t)blockIdx.y * 64 + tb * 4 + i) * 512 + h0 + tc * 4 + j] = acc[i][j];
}

// =====================================================================
// Block attention: one CTA per (b, n); tile cached in smem for 2nd pass.
// =====================================================================
__global__ __launch_bounds__(512) void k_attn(const float* __restrict__ enc,
                                              float* __restrict__ out) {
    extern __shared__ float sm[];
    float* tile = sm;                       // 64*512
    float* u_s  = sm + 64 * 512;            // 512
    float* sc   = sm + 64 * 512 + 512;      // 64
    const int t = threadIdx.x, w = t >> 5, lane = t & 31;
    const int bn = blockIdx.x;
    const int b = bn >> 5;

    {   float s = 0.f;
#pragma unroll
        for (int p = 0; p < 8; ++p) s += g_upart[((size_t)p * 64 + b) * 512 + t];
        u_s[t] = s;
    }
    __syncthreads();

    float uu[4][4];
#pragma unroll
    for (int j = 0; j < 4; ++j) {
        float4 q = *(const float4*)&u_s[(lane + 32 * j) * 4];
        uu[j][0] = q.x; uu[j][1] = q.y; uu[j][2] = q.z; uu[j][3] = q.w;
    }
    const float4* eo4 = (const float4*)(enc + (size_t)bn * (64 * 512));
    float4* tile4 = (float4*)tile;
#pragma unroll
    for (int i = 0; i < 4; ++i) {
        const int l = w * 4 + i;
        float acc = 0.f;
#pragma unroll
        for (int j = 0; j < 4; ++j) {
            float4 v = eo4[l * 128 + lane + 32 * j];
            tile4[l * 128 + lane + 32 * j] = v;
            acc += v.x * uu[j][0] + v.y * uu[j][1] + v.z * uu[j][2] + v.w * uu[j][3];
        }
#pragma unroll
        for (int o = 16; o; o >>= 1) acc += __shfl_xor_sync(0xffffffffu, acc, o);
        if (lane == 0) sc[l] = acc;
    }
    __syncthreads();

    if (w == 0) {
        float s0 = sc[lane], s1 = sc[lane + 32];
        float m = fmaxf(s0, s1);
#pragma unroll
        for (int o = 16; o; o >>= 1) m = fmaxf(m, __shfl_xor_sync(0xffffffffu, m, o));
        float e0 = __expf(s0 - m), e1 = __expf(s1 - m);
        float s = e0 + e1;
#pragma unroll
        for (int o = 16; o; o >>= 1) s += __shfl_xor_sync(0xffffffffu, s, o);
        float inv = 1.f / s;
        float w0 = e0 * inv, w1 = e1 * inv;
        sc[lane] = w0; sc[lane + 32] = w1;
        out[OFF_ATTN + (size_t)bn * 64 + lane] = w0;
        out[OFF_ATTN + (size_t)bn * 64 + lane + 32] = w1;
    }
    __syncthreads();

    float acc = 0.f;
#pragma unroll 8
    for (int l = 0; l < 64; ++l) acc += sc[l] * tile[l * 512 + t];
    g_bctx[(size_t)bn * 512 + t] = acc;
}

// =====================================================================
// context reduce + embedding gather + concat inputs (+bf16 of ctx)
// =====================================================================
__global__ __launch_bounds__(512) void k_ctx(const float* __restrict__ baw,
                                             const float* __restrict__ emb,
                                             const int* __restrict__ ids,
                                             float* __restrict__ out) {
    const int b = blockIdx.x, h = threadIdx.x;
    float acc = 0.f;
#pragma unroll 8
    for (int n = 0; n < 32; ++n)
        acc += baw[b * 32 + n] * g_bctx[((size_t)b * 32 + n) * 512 + h];
    out[OFF_CTX + (size_t)b * 512 + h] = acc;
    g_x0[b * 1024 + 512 + h] = acc;
    ((__nv_bfloat16*)g_x1h4)[b * 1024 + 512 + h] = __float2bfloat16(acc);
    g_x0[b * 1024 + h] = emb[(size_t)ids[b] * 512 + h];
}

// =====================================================================
// FFMA2 GEMM body (gate GEMMs): double-buffered, register prefetch.
// r-tile = 64 -> smem 51.2KB -> 4 CTAs/SM (was 2), grid.x = 24.
// =====================================================================
__device__ __forceinline__ void ffma2(unsigned long long& d, unsigned long long a,
                                      unsigned long long b) {
    asm("fma.rn.f32x2 %0, %1, %2, %0;" : "+l"(d) : "l"(a), "l"(b));
}

#define AS_ULL 1088              // 32 * 34
#define WD_ULL 2112              // 32 * 66
#define GEMM_SMEM_BYTES ((2 * AS_ULL + 2 * WD_ULL) * 8)   // 51200

__device__ __forceinline__ void gemm_body(const float* __restrict__ A,
                                          const float* __restrict__ W,
                                          float* __restrict__ C,
                                          const int K, const int ks, const int ke) {
    extern __shared__ unsigned long long smu[];
    unsigned long long* As = smu;                 // 2 x [kk][34 ull]
    unsigned long long* Wd = smu + 2 * AS_ULL;    // 2 x [kk][66 ull]
    const int t = threadIdx.x;
    const int r0 = blockIdx.x * 64;
    const int tb = t & 15, tc = t >> 4;
    unsigned long long acc[2][4] = {};
    float4 pa[2], pw[2];

    auto ldT = [&](int k0) {
#pragma unroll
        for (int j = 0; j < 2; ++j) {             // A: 64b x 32kk
            int lin = (t + j * 256) * 4;
            int bb = lin >> 5, kk = lin & 31;
            pa[j] = *(const float4*)(A + (size_t)bb * K + k0 + kk);
        }
#pragma unroll
        for (int j = 0; j < 2; ++j) {             // W: 64r x 32kk
            int lin = (t + j * 256) * 4;
            int rr = lin >> 5, kk = lin & 31;
            pw[j] = *(const float4*)(W + (size_t)(r0 + rr) * K + k0 + kk);
        }
    };
    auto stT = [&](int buf) {
        float*  asf = (float*)(As + buf * AS_ULL);
        float2* wdf = (float2*)(Wd + buf * WD_ULL);
#pragma unroll
        for (int j = 0; j < 2; ++j) {
            int lin = (t + j * 256) * 4;
            int bb = lin >> 5, kk = lin & 31;
            asf[(kk + 0) * 68 + bb] = pa[j].x; asf[(kk + 1) * 68 + bb] = pa[j].y;
            asf[(kk + 2) * 68 + bb] = pa[j].z; asf[(kk + 3) * 68 + bb] = pa[j].w;
        }
#pragma unroll
        for (int j = 0; j < 2; ++j) {
            int lin = (t + j * 256) * 4;
            int rr = lin >> 5, kk = lin & 31;
            wdf[(kk + 0) * 66 + rr] = make_float2(pw[j].x, pw[j].x);
            wdf[(kk + 1) * 66 + rr] = make_float2(pw[j].y, pw[j].y);
            wdf[(kk + 2) * 66 + rr] = make_float2(pw[j].z, pw[j].z);
            wdf[(kk + 3) * 66 + rr] = make_float2(pw[j].w, pw[j].w);
        }
    };

    ldT(ks);
    stT(0);
    __syncthreads();
    int buf = 0;
    for (int k0 = ks; k0 < ke; k0 += 32) {
        const bool more = (k0 + 32) < ke;
        if (more) ldT(k0 + 32);
        const unsigned long long* Ab = As + buf * AS_ULL;
        const unsigned long long* Wb = Wd + buf * WD_ULL;
#pragma unroll 8
        for (int kk = 0; kk < 32; ++kk) {
            ulonglong2 av = *(const ulonglong2*)&Ab[kk * 34 + tb * 2];
#pragma unroll
            for (int j2 = 0; j2 < 2; ++j2) {
                ulonglong2 wv = *(const ulonglong2*)&Wb[kk * 66 + tc * 4 + j2 * 2];
                ffma2(acc[0][j2 * 2 + 0], av.x, wv.x);
                ffma2(acc[1][j2 * 2 + 0], av.y, wv.x);
                ffma2(acc[0][j2 * 2 + 1], av.x, wv.y);
                ffma2(acc[1][j2 * 2 + 1], av.y, wv.y);
            }
        }
        if (more) stT(buf ^ 1);
        __syncthreads();
        buf ^= 1;
    }
#pragma unroll
    for (int p = 0; p < 2; ++p)
#pragma unroll
        for (int j = 0; j < 4; ++j) {
            int r = r0 + tc * 4 + j;
            float lo = __uint_as_float((unsigned)(acc[p][j] & 0xffffffffULL));
            float hi = __uint_as_float((unsigned)(acc[p][j] >> 32));
            int b = tb * 4 + 2 * p;
            C[(size_t)b * 1536 + r] = lo;
            C[(size_t)(b + 1) * 1536 + r] = hi;
        }
}

// gate GEMMs, k-split chunk 64: y selects gx/gh, z selects chunk
__global__ __launch_bounds__(256) void k_gates(const float* A0, const float* W0, int K0,
                                               const float* A1, const float* W1, int K1) {
    const int z = blockIdx.z;
    if (blockIdx.y == 0) {
        if (z * 64 >= K0) return;
        gemm_body(A0, W0, g_gxp + (size_t)z * 64 * 1536, K0, z * 64, z * 64 + 64);
    } else {
        if (z * 64 >= K1) return;
        gemm_body(A1, W1, g_ghp + (size_t)z * 64 * 1536, K1, z * 64, z * 64 + 64);
    }
}

// =====================================================================
// GRU pointwise + partial reduction + biases (+bf16 of h1 into x1)
// =====================================================================
__global__ __launch_bounds__(512) void k_gru(int nzx, int nzh, int wr_x1,
                                             const float* __restrict__ bih,
                                             const float* __restrict__ bhh,
                                             const float* __restrict__ hprev,
                                             float* __restrict__ hnew) {
    const int b = blockIdx.x, j = threadIdx.x;
    float xr = bih[j], xz = bih[512 + j], xn = bih[1024 + j];
    for (int z = 0; z < nzx; ++z) {
        const float* p = g_gxp + ((size_t)z * 64 + b) * 1536;
        xr += p[j]; xz += p[512 + j]; xn += p[1024 + j];
    }
    float hr = bhh[j], hz = bhh[512 + j], hn = bhh[1024 + j];
    for (int z = 0; z < nzh; ++z) {
        const float* p = g_ghp + ((size_t)z * 64 + b) * 1536;
        hr += p[j]; hz += p[512 + j]; hn += p[1024 + j];
    }
    float h = hprev[(size_t)b * 512 + j];
    float r = 1.f / (1.f + __expf(-(xr + hr)));
    float z_ = 1.f / (1.f + __expf(-(xz + hz)));
    float n = tanhf(xn + r * hn);
    float hv = (1.f - z_) * n + z_ * h;
    hnew[(size_t)b * 512 + j] = hv;
    if (wr_x1)
        ((__nv_bfloat16*)g_x1h4)[b * 1024 + j] = __float2bfloat16(hv);
}

// =====================================================================
// Output projection (EXACT Round-9 config, measured best): bf16 mma.sync,
// k-permuted fragments, 256-col tiles (grid 197), depth-1 W prefetch.
// Epilogue fuses per-row (max,sumexp) partials.
// =====================================================================
__device__ __forceinline__ void olmerge(float& m, float& s, float v) {
    float nm = fmaxf(m, v);
    s = s * __expf(m - nm) + __expf(v - nm);
    m = nm;
}

__global__ __launch_bounds__(256, 2) void k_proj(const float* __restrict__ W,
                                                 const float* __restrict__ bias,
                                                 float* __restrict__ out) {
    __shared__ uint4 sA[64 * 17];          // A bf16 [row][128-k chunk], pad 17
    __shared__ float2 sRed[64 * 8];        // per-row per-warp (max,sum)
    const int t = threadIdx.x, w = t >> 5, lane = t & 31;
    const int r0 = blockIdx.x * 256 + w * 32;
    const int qr = lane >> 2, qk = lane & 3;

    float acc[4][4][4];
#pragma unroll
    for (int a = 0; a < 4; ++a)
#pragma unroll
        for (int c = 0; c < 4; ++c)
#pragma unroll
            for (int d = 0; d < 4; ++d) acc[a][c][d] = 0.f;

    float4 wraw[4];
    auto ldW = [&](int step, float4* dst) {
        const int koff = step * 16 + 4 * qk;
#pragma unroll
        for (int nf = 0; nf < 4; ++nf) {
            int r = r0 + nf * 8 + qr;
            dst[nf] = make_float4(0.f, 0.f, 0.f, 0.f);
            if (r < V_) dst[nf] = *(const float4*)(W + (size_t)r * 1024 + koff);
        }
    };

    ldW(0, wraw);
    for (int step = 0; step < 64; ++step) {
        const int s = step & 7;
        if (s == 0) {   // stage A chunk [64 rows][128 k] as bf16
            const int kc8 = (step >> 3) << 4;
            __syncthreads();
#pragma unroll
            for (int j = 0; j < 4; ++j) {
                int idx = t + j * 256;
                int row = idx >> 4, c8 = idx & 15;
                sA[row * 17 + c8] = g_x1h4[row * 128 + kc8 + c8];
            }
            __syncthreads();
        }
        float4 nraw[4];
        if (step < 63) ldW(step + 1, nraw);

        unsigned b0[4], b1[4];
#pragma unroll
        for (int nf = 0; nf < 4; ++nf) {
            asm("cvt.rn.bf16x2.f32 %0, %1, %2;" : "=r"(b0[nf])
                : "f"(wraw[nf].y), "f"(wraw[nf].x));
            asm("cvt.rn.bf16x2.f32 %0, %1, %2;" : "=r"(b1[nf])
                : "f"(wraw[nf].w), "f"(wraw[nf].z));
        }
#pragma unroll
        for (int mf = 0; mf < 4; ++mf) {
            const char* base = (const char*)sA + s * 32 + qk * 8;
            uint2 alo = *(const uint2*)(base + (mf * 16 + qr) * 272);
            uint2 ahi = *(const uint2*)(base + (mf * 16 + qr + 8) * 272);
#pragma unroll
            for (int nf = 0; nf < 4; ++nf) {
                asm volatile(
                    "mma.sync.aligned.m16n8k16.row.col.f32.bf16.bf16.f32 "
                    "{%0,%1,%2,%3}, {%4,%5,%6,%7}, {%8,%9}, {%0,%1,%2,%3};"
                    : "+f"(acc[mf][nf][0]), "+f"(acc[mf][nf][1]),
                      "+f"(acc[mf][nf][2]), "+f"(acc[mf][nf][3])
                    : "r"(alo.x), "r"(ahi.x), "r"(alo.y), "r"(ahi.y),
                      "r"(b0[nf]), "r"(b1[nf]));
            }
        }
#pragma unroll
        for (int nf = 0; nf < 4; ++nf) wraw[nf] = nraw[nf];
    }

    // ---- epilogue: bias + store + fused per-row (max, sumexp) partials ----
    float rm[4][2], rs[4][2];
#pragma unroll
    for (int mf = 0; mf < 4; ++mf) { rm[mf][0] = rm[mf][1] = -3.0e38f;
                                     rs[mf][0] = rs[mf][1] = 0.f; }
#pragma unroll
    for (int mf = 0; mf < 4; ++mf) {
        const int m0 = mf * 16 + qr;
#pragma unroll
        for (int nf = 0; nf < 4; ++nf) {
            int rr = r0 + nf * 8 + 2 * qk;
            if (rr < V_) {
                float bv = bias[rr];
                float l0 = acc[mf][nf][0] + bv, l2 = acc[mf][nf][2] + bv;
                out[(size_t)m0 * V_ + rr] = l0;
                out[(size_t)(m0 + 8) * V_ + rr] = l2;
                olmerge(rm[mf][0], rs[mf][0], l0);
                olmerge(rm[mf][1], rs[mf][1], l2);
            }
            if (rr + 1 < V_) {
                float bv = bias[rr + 1];
                float l1 = acc[mf][nf][1] + bv, l3 = acc[mf][nf][3] + bv;
                out[(size_t)m0 * V_ + rr + 1] = l1;
                out[(size_t)(m0 + 8) * V_ + rr + 1] = l3;
                olmerge(rm[mf][0], rs[mf][0], l1);
                olmerge(rm[mf][1], rs[mf][1], l3);
            }
        }
    }
    // reduce across the 4 qk threads of each quad
#pragma unroll
    for (int mf = 0; mf < 4; ++mf)
#pragma unroll
        for (int hf = 0; hf < 2; ++hf) {
#pragma unroll
            for (int o = 1; o <= 2; o <<= 1) {
                float om = __shfl_xor_sync(0xffffffffu, rm[mf][hf], o);
                float os = __shfl_xor_sync(0xffffffffu, rs[mf][hf], o);
                float nm = fmaxf(rm[mf][hf], om);
                rs[mf][hf] = rs[mf][hf] * __expf(rm[mf][hf] - nm) + os * __expf(om - nm);
                rm[mf][hf] = nm;
            }
            if (qk == 0)
                sRed[(mf * 16 + qr + 8 * hf) * 8 + w] = make_float2(rm[mf][hf], rs[mf][hf]);
        }
    __syncthreads();
    if (t < 64) {
        float m = -3.0e38f, s = 0.f;
#pragma unroll
        for (int i = 0; i < 8; ++i) {
            float2 p = sRed[t * 8 + i];
            float nm = fmaxf(m, p.x);
            s = s * __expf(m - nm) + p.y * __expf(p.x - nm);
            m = nm;
        }
        g_pm[(size_t)blockIdx.x * 64 + t] = make_float2(m, s);
    }
}

// =====================================================================
// combine per-CTA lsm partials -> per-row lse (197 partials per row)
// =====================================================================
__global__ __launch_bounds__(256) void k_lsm_comb() {
    const int b = blockIdx.x, t = threadIdx.x;
    __shared__ float redm[8], reds[8];
    float m = -3.0e38f, s = 0.f;
    if (t < NPROJ) {
        float2 p = g_pm[(size_t)t * 64 + b];
        m = p.x; s = p.y;
    }
#pragma unroll
    for (int o = 16; o; o >>= 1) {
        float om = __shfl_xor_sync(0xffffffffu, m, o);
        float os = __shfl_xor_sync(0xffffffffu, s, o);
        float nm = fmaxf(m, om);
        s = s * __expf(m - nm) + os * __expf(om - nm);
        m = nm;
    }
    if ((t & 31) == 0) { redm[t >> 5] = m; reds[t >> 5] = s; }
    __syncthreads();
    if (t == 0) {
        float mm = redm[0], ss = reds[0];
        for (int i = 1; i < 8; ++i) {
            float nm = fmaxf(mm, redm[i]);
            ss = ss * __expf(mm - nm) + reds[i] * __expf(redm[i] - nm);
            mm = nm;
        }
        g_lsmv[b] = mm + logf(ss);
    }
}

// =====================================================================
// subtract lse in place
// =====================================================================
#define LSM_CHUNK 6284   // ceil(50257/8)
__global__ __launch_bounds__(512) void k_lsm2(float* __restrict__ out) {
    const int c = blockIdx.x, b = blockIdx.y, t = threadIdx.x;
    float* row = out + (size_t)b * V_;
    const float lse = g_lsmv[b];
    const int i0 = c * LSM_CHUNK, i1 = min(i0 + LSM_CHUNK, V_);
    for (int i = i0 + t; i < i1; i += 512) row[i] -= lse;
}

// =====================================================================
extern "C" void kernel_launch(void* const* d_in, const int* in_sizes, int n_in,
                              void* d_out, int out_size) {
    const int* ids = (const int*)d_in[0];
    const float* hidden = (const float*)d_in[1];
    const float* baw = (const float*)d_in[2];
    const float* enc = (const float*)d_in[3];
    int o = (n_in >= 5 && in_sizes[4] == 1) ? 1 : 0;
    const float* emb    = (const float*)d_in[4 + o];
    const float* attn_W = (const float*)d_in[5 + o];
    // attn_b (d_in[6+o]) is softmax-shift invariant — unused
    const float* W_ih0  = (const float*)d_in[7 + o];
    const float* W_hh0  = (const float*)d_in[8 + o];
    const float* b_ih0  = (const float*)d_in[9 + o];
    const float* b_hh0  = (const float*)d_in[10 + o];
    const float* W_ih1  = (const float*)d_in[11 + o];
    const float* W_hh1  = (const float*)d_in[12 + o];
    const float* b_ih1  = (const float*)d_in[13 + o];
    const float* b_hh1  = (const float*)d_in[14 + o];
    const float* out_W  = (const float*)d_in[15 + o];
    const float* out_b  = (const float*)d_in[16 + o];
    float* out = (float*)d_out;

    float* p_x0;
    cudaGetSymbolAddress((void**)&p_x0, g_x0);

    const int attn_smem = (64 * 512 + 512 + 64) * 4;  // 133376 B
    cudaFuncSetAttribute(k_attn, cudaFuncAttributeMaxDynamicSharedMemorySize, attn_smem);
    cudaFuncSetAttribute(k_gates, cudaFuncAttributeMaxDynamicSharedMemorySize, GEMM_SMEM_BYTES);

    // 1. u = h1 @ attn_W (8x8 partials)
    k_u_part<<<dim3(8, 8), 256>>>(hidden, attn_W);
    // 2. per-block attention
    k_attn<<<2048, 512, attn_smem>>>(enc, out);
    // 3. context reduce + embedding gather + concat buffers
    k_ctx<<<64, 512>>>(baw, emb, ids, out);
    // 4. GRU layer 0 gates (k-split 64, r-tile 64), pointwise+reduce
    k_gates<<<dim3(24, 2, 16), 256, GEMM_SMEM_BYTES>>>(p_x0, W_ih0, 1024,
                                                       hidden, W_hh0, 512);
    k_gru<<<64, 512>>>(16, 8, 0, b_ih0, b_hh0, hidden, out + OFF_NH);
    // 5. GRU layer 1 gates, pointwise+reduce (writes x1 bf16)
    k_gates<<<dim3(24, 2, 8), 256, GEMM_SMEM_BYTES>>>(out + OFF_NH, W_ih1, 512,
                                                      hidden + 64 * 512, W_hh1, 512);
    k_gru<<<64, 512>>>(8, 8, 1, b_ih1, b_hh1, hidden + 64 * 512,
                       out + OFF_NH + 64 * 512);
    // 6. output projection (fused lsm partials), 256-col tiles (R9 config)
    k_proj<<<NPROJ, 256>>>(out_W, out_b, out);
    // 7. combine lse + subtract
    k_lsm_comb<<<64, 256>>>();
    k_lsm2<<<dim3(8, 64), 512>>>(out);
}

// round 14
// speedup vs baseline: 1.7395x; 1.0034x over previous
#include <cuda_runtime.h>
#include <cuda_bf16.h>
#include <cstdint>

#define B_ 64
#define H_ 512
#define V_ 50257
#define NPROJ 197            // ceil(V_/256)

// ---- scratch (__device__ globals; no allocation allowed) ----
__device__ float g_upart[8 * 64 * 512];      // partial u = h1 @ attn_W
__device__ float g_bctx[64 * 32 * 512];      // block contexts
__device__ float g_x0[64 * 1024];            // [embedded | context] fp32 (layer-0 input)
__device__ uint4 g_x1h4[8192];               // x1 bf16  [64][1024]
__device__ float g_gxp[16 * 64 * 1536];      // gx partials (k-split)
__device__ float g_ghp[8 * 64 * 1536];       // gh partials (k-split)
__device__ float2 g_pm[NPROJ * 64];          // per-CTA per-row (max, sumexp)
__device__ float g_lsmv[64];                 // per-row lse

// ---- output layout: log_probs, new_hidden[2,B,H], context[B,H], attn_w[B,32,64]
#define OFF_NH   ((size_t)B_ * V_)
#define OFF_CTX  (OFF_NH + (size_t)2 * B_ * H_)
#define OFF_ATTN (OFF_CTX + (size_t)B_ * H_)

// =====================================================================
// u partials: u[b,h] = sum_g h1[b,g] * attn_W[g,h]
// =====================================================================
__global__ __launch_bounds__(256) void k_u_part(const float* __restrict__ hidden,
                                                const float* __restrict__ attn_W) {
    __shared__ float Hs[64 * 65];
    __shared__ float Ws[64 * 65];
    const int t = threadIdx.x;
    const int h0 = blockIdx.x * 64, g0 = blockIdx.y * 64;
    const float* h1 = hidden + 64 * 512;  // hidden[-1]
#pragma unroll
    for (int j = 0; j < 4; ++j) {
        int lin = (t + j * 256) * 4;
        int bb = lin >> 6, kk = lin & 63;
        float4 v = *(const float4*)(h1 + (size_t)bb * 512 + g0 + kk);
        Hs[bb * 65 + kk + 0] = v.x; Hs[bb * 65 + kk + 1] = v.y;
        Hs[bb * 65 + kk + 2] = v.z; Hs[bb * 65 + kk + 3] = v.w;
    }
#pragma unroll
    for (int j = 0; j < 4; ++j) {
        int lin = (t + j * 256) * 4;
        int kk = lin >> 6, hh = lin & 63;
        float4 v = *(const float4*)(attn_W + (size_t)(g0 + kk) * 512 + h0 + hh);
        Ws[(hh + 0) * 65 + kk] = v.x; Ws[(hh + 1) * 65 + kk] = v.y;
        Ws[(hh + 2) * 65 + kk] = v.z; Ws[(hh + 3) * 65 + kk] = v.w;
    }
    __syncthreads();
    const int tb = t & 15, tc = t >> 4;
    float acc[4][4] = {};
#pragma unroll 8
    for (int kk = 0; kk < 64; ++kk) {
        float a0 = Hs[(tb * 4 + 0) * 65 + kk];
        float a1 = Hs[(tb * 4 + 1) * 65 + kk];
        float a2 = Hs[(tb * 4 + 2) * 65 + kk];
        float a3 = Hs[(tb * 4 + 3) * 65 + kk];
#pragma unroll
        for (int j = 0; j < 4; ++j) {
            float wv = Ws[(tc * 4 + j) * 65 + kk];
            acc[0][j] += a0 * wv; acc[1][j] += a1 * wv;
            acc[2][j] += a2 * wv; acc[3][j] += a3 * wv;
        }
    }
#pragma unroll
    for (int i = 0; i < 4; ++i)
#pragma unroll
        for (int j = 0; j < 4; ++j)
            g_upart[((size_t)blockIdx.y * 64 + tb * 4 + i) * 512 + h0 + tc * 4 + j] = acc[i][j];
}

// =====================================================================
// Block attention: one CTA per (b, n); tile cached in smem for 2nd pass.
// =====================================================================
__global__ __launch_bounds__(512) void k_attn(const float* __restrict__ enc,
                                              float* __restrict__ out) {
    extern __shared__ float sm[];
    float* tile = sm;                       // 64*512
    float* u_s  = sm + 64 * 512;            // 512
    float* sc   = sm + 64 * 512 + 512;      // 64
    const int t = threadIdx.x, w = t >> 5, lane = t & 31;
    const int bn = blockIdx.x;
    const int b = bn >> 5;

    {   float s = 0.f;
#pragma unroll
        for (int p = 0; p < 8; ++p) s += g_upart[((size_t)p * 64 + b) * 512 + t];
        u_s[t] = s;
    }
    __syncthreads();

    float uu[4][4];
#pragma unroll
    for (int j = 0; j < 4; ++j) {
        float4 q = *(const float4*)&u_s[(lane + 32 * j) * 4];
        uu[j][0] = q.x; uu[j][1] = q.y; uu[j][2] = q.z; uu[j][3] = q.w;
    }
    const float4* eo4 = (const float4*)(enc + (size_t)bn * (64 * 512));
    float4* tile4 = (float4*)tile;
#pragma unroll
    for (int i = 0; i < 4; ++i) {
        const int l = w * 4 + i;
        float acc = 0.f;
#pragma unroll
        for (int j = 0; j < 4; ++j) {
            float4 v = eo4[l * 128 + lane + 32 * j];
            tile4[l * 128 + lane + 32 * j] = v;
            acc += v.x * uu[j][0] + v.y * uu[j][1] + v.z * uu[j][2] + v.w * uu[j][3];
        }
#pragma unroll
        for (int o = 16; o; o >>= 1) acc += __shfl_xor_sync(0xffffffffu, acc, o);
        if (lane == 0) sc[l] = acc;
    }
    __syncthreads();

    if (w == 0) {
        float s0 = sc[lane], s1 = sc[lane + 32];
        float m = fmaxf(s0, s1);
#pragma unroll
        for (int o = 16; o; o >>= 1) m = fmaxf(m, __shfl_xor_sync(0xffffffffu, m, o));
        float e0 = __expf(s0 - m), e1 = __expf(s1 - m);
        float s = e0 + e1;
#pragma unroll
        for (int o = 16; o; o >>= 1) s += __shfl_xor_sync(0xffffffffu, s, o);
        float inv = 1.f / s;
        float w0 = e0 * inv, w1 = e1 * inv;
        sc[lane] = w0; sc[lane + 32] = w1;
        out[OFF_ATTN + (size_t)bn * 64 + lane] = w0;
        out[OFF_ATTN + (size_t)bn * 64 + lane + 32] = w1;
    }
    __syncthreads();

    float acc = 0.f;
#pragma unroll 8
    for (int l = 0; l < 64; ++l) acc += sc[l] * tile[l * 512 + t];
    g_bctx[(size_t)bn * 512 + t] = acc;
}

// =====================================================================
// context reduce + embedding gather + concat inputs (+bf16 of ctx)
// =====================================================================
__global__ __launch_bounds__(512) void k_ctx(const float* __restrict__ baw,
                                             const float* __restrict__ emb,
                                             const int* __restrict__ ids,
                                             float* __restrict__ out) {
    const int b = blockIdx.x, h = threadIdx.x;
    float acc = 0.f;
#pragma unroll 8
    for (int n = 0; n < 32; ++n)
        acc += baw[b * 32 + n] * g_bctx[((size_t)b * 32 + n) * 512 + h];
    out[OFF_CTX + (size_t)b * 512 + h] = acc;
    g_x0[b * 1024 + 512 + h] = acc;
    ((__nv_bfloat16*)g_x1h4)[b * 1024 + 512 + h] = __float2bfloat16(acc);
    g_x0[b * 1024 + h] = emb[(size_t)ids[b] * 512 + h];
}

// =====================================================================
// FFMA2 GEMM body (gate GEMMs): double-buffered, register prefetch.
// r-tile 64, smem 51.2KB, 4 CTAs/SM (Round-12 measured config).
// =====================================================================
__device__ __forceinline__ void ffma2(unsigned long long& d, unsigned long long a,
                                      unsigned long long b) {
    asm("fma.rn.f32x2 %0, %1, %2, %0;" : "+l"(d) : "l"(a), "l"(b));
}

#define AS_ULL 1088              // 32 * 34
#define WD_ULL 2112              // 32 * 66
#define GEMM_SMEM_BYTES ((2 * AS_ULL + 2 * WD_ULL) * 8)   // 51200

__device__ __forceinline__ void gemm_body(const float* __restrict__ A,
                                          const float* __restrict__ W,
                                          float* __restrict__ C,
                                          const int K, const int ks, const int ke) {
    extern __shared__ unsigned long long smu[];
    unsigned long long* As = smu;                 // 2 x [kk][34 ull]
    unsigned long long* Wd = smu + 2 * AS_ULL;    // 2 x [kk][66 ull]
    const int t = threadIdx.x;
    const int r0 = blockIdx.x * 64;
    const int tb = t & 15, tc = t >> 4;
    unsigned long long acc[2][4] = {};
    float4 pa[2], pw[2];

    auto ldT = [&](int k0) {
#pragma unroll
        for (int j = 0; j < 2; ++j) {             // A: 64b x 32kk
            int lin = (t + j * 256) * 4;
            int bb = lin >> 5, kk = lin & 31;
            pa[j] = *(const float4*)(A + (size_t)bb * K + k0 + kk);
        }
#pragma unroll
        for (int j = 0; j < 2; ++j) {             // W: 64r x 32kk
            int lin = (t + j * 256) * 4;
            int rr = lin >> 5, kk = lin & 31;
            pw[j] = *(const float4*)(W + (size_t)(r0 + rr) * K + k0 + kk);
        }
    };
    auto stT = [&](int buf) {
        float*  asf = (float*)(As + buf * AS_ULL);
        float2* wdf = (float2*)(Wd + buf * WD_ULL);
#pragma unroll
        for (int j = 0; j < 2; ++j) {
            int lin = (t + j * 256) * 4;
            int bb = lin >> 5, kk = lin & 31;
            asf[(kk + 0) * 68 + bb] = pa[j].x; asf[(kk + 1) * 68 + bb] = pa[j].y;
            asf[(kk + 2) * 68 + bb] = pa[j].z; asf[(kk + 3) * 68 + bb] = pa[j].w;
        }
#pragma unroll
        for (int j = 0; j < 2; ++j) {
            int lin = (t + j * 256) * 4;
            int rr = lin >> 5, kk = lin & 31;
            wdf[(kk + 0) * 66 + rr] = make_float2(pw[j].x, pw[j].x);
            wdf[(kk + 1) * 66 + rr] = make_float2(pw[j].y, pw[j].y);
            wdf[(kk + 2) * 66 + rr] = make_float2(pw[j].z, pw[j].z);
            wdf[(kk + 3) * 66 + rr] = make_float2(pw[j].w, pw[j].w);
        }
    };

    ldT(ks);
    stT(0);
    __syncthreads();
    int buf = 0;
    for (int k0 = ks; k0 < ke; k0 += 32) {
        const bool more = (k0 + 32) < ke;
        if (more) ldT(k0 + 32);
        const unsigned long long* Ab = As + buf * AS_ULL;
        const unsigned long long* Wb = Wd + buf * WD_ULL;
#pragma unroll 8
        for (int kk = 0; kk < 32; ++kk) {
            ulonglong2 av = *(const ulonglong2*)&Ab[kk * 34 + tb * 2];
#pragma unroll
            for (int j2 = 0; j2 < 2; ++j2) {
                ulonglong2 wv = *(const ulonglong2*)&Wb[kk * 66 + tc * 4 + j2 * 2];
                ffma2(acc[0][j2 * 2 + 0], av.x, wv.x);
                ffma2(acc[1][j2 * 2 + 0], av.y, wv.x);
                ffma2(acc[0][j2 * 2 + 1], av.x, wv.y);
                ffma2(acc[1][j2 * 2 + 1], av.y, wv.y);
            }
        }
        if (more) stT(buf ^ 1);
        __syncthreads();
        buf ^= 1;
    }
#pragma unroll
    for (int p = 0; p < 2; ++p)
#pragma unroll
        for (int j = 0; j < 4; ++j) {
            int r = r0 + tc * 4 + j;
            float lo = __uint_as_float((unsigned)(acc[p][j] & 0xffffffffULL));
            float hi = __uint_as_float((unsigned)(acc[p][j] >> 32));
            int b = tb * 4 + 2 * p;
            C[(size_t)b * 1536 + r] = lo;
            C[(size_t)(b + 1) * 1536 + r] = hi;
        }
}

// gate GEMMs, k-split chunk 64: y selects gx/gh, z selects chunk
__global__ __launch_bounds__(256) void k_gates(const float* A0, const float* W0, int K0,
                                               const float* A1, const float* W1, int K1) {
    const int z = blockIdx.z;
    if (blockIdx.y == 0) {
        if (z * 64 >= K0) return;
        gemm_body(A0, W0, g_gxp + (size_t)z * 64 * 1536, K0, z * 64, z * 64 + 64);
    } else {
        if (z * 64 >= K1) return;
        gemm_body(A1, W1, g_ghp + (size_t)z * 64 * 1536, K1, z * 64, z * 64 + 64);
    }
}

// =====================================================================
// GRU pointwise + partial reduction + biases (+bf16 of h1 into x1)
// =====================================================================
__global__ __launch_bounds__(512) void k_gru(int nzx, int nzh, int wr_x1,
                                             const float* __restrict__ bih,
                                             const float* __restrict__ bhh,
                                             const float* __restrict__ hprev,
                                             float* __restrict__ hnew) {
    const int b = blockIdx.x, j = threadIdx.x;
    float xr = bih[j], xz = bih[512 + j], xn = bih[1024 + j];
    for (int z = 0; z < nzx; ++z) {
        const float* p = g_gxp + ((size_t)z * 64 + b) * 1536;
        xr += p[j]; xz += p[512 + j]; xn += p[1024 + j];
    }
    float hr = bhh[j], hz = bhh[512 + j], hn = bhh[1024 + j];
    for (int z = 0; z < nzh; ++z) {
        const float* p = g_ghp + ((size_t)z * 64 + b) * 1536;
        hr += p[j]; hz += p[512 + j]; hn += p[1024 + j];
    }
    float h = hprev[(size_t)b * 512 + j];
    float r = 1.f / (1.f + __expf(-(xr + hr)));
    float z_ = 1.f / (1.f + __expf(-(xz + hz)));
    float n = tanhf(xn + r * hn);
    float hv = (1.f - z_) * n + z_ * h;
    hnew[(size_t)b * 512 + j] = hv;
    if (wr_x1)
        ((__nv_bfloat16*)g_x1h4)[b * 1024 + j] = __float2bfloat16(hv);
}

// =====================================================================
// Output projection: bf16 mma.sync with cp.async-pipelined W (4 stages x
// 16KB, 3 in flight -> ~48KB/CTA in-flight DRAM traffic, no register
// cost). 256-col tiles, grid 197, 2 CTAs/SM. k-permuted fragments:
// thread quad's canonical k-slots hold k {4qk..4qk+3} -> W frag is ONE
// LDS.128 from the staged tile. Epilogue fuses lsm partials.
// =====================================================================
__device__ __forceinline__ void olmerge(float& m, float& s, float v) {
    float nm = fmaxf(m, v);
    s = s * __expf(m - nm) + __expf(v - nm);
    m = nm;
}

#define PROJ_SA_BYTES  17408                 // 64*17 uint4
#define PROJ_SW_BYTES  65536                 // 4 stages * 256 rows * 16 k * 4B
#define PROJ_SMEM_BYTES (PROJ_SA_BYTES + PROJ_SW_BYTES + 4096)

__global__ __launch_bounds__(256, 2) void k_proj(const float* __restrict__ W,
                                                 const float* __restrict__ bias,
                                                 float* __restrict__ out) {
    extern __shared__ char psm[];
    uint4*  sA   = (uint4*)psm;                              // [64][17]
    float*  sW   = (float*)(psm + PROJ_SA_BYTES);            // [4][256][16]
    float2* sRed = (float2*)(psm + PROJ_SA_BYTES + PROJ_SW_BYTES); // [64][8]
    const int t = threadIdx.x, w = t >> 5, lane = t & 31;
    const int r0c = blockIdx.x * 256;
    const int r0 = r0c + w * 32;
    const int qr = lane >> 2, qk = lane & 3;

    float acc[4][4][4];
#pragma unroll
    for (int a = 0; a < 4; ++a)
#pragma unroll
        for (int c = 0; c < 4; ++c)
#pragma unroll
            for (int d = 0; d < 4; ++d) acc[a][c][d] = 0.f;

    // stage W[r0c..r0c+255][step*16..+16) into slot step&3 via cp.async
    auto stageW = [&](int step) {
        if (step < 64) {
            const int slot = step & 3;
            const int kc = step * 16;
#pragma unroll
            for (int j = 0; j < 4; ++j) {
                int idx = t + j * 256;           // 0..1023
                int row = idx >> 2, kq = idx & 3;
                if (r0c + row < V_) {
                    unsigned daddr = (unsigned)__cvta_generic_to_shared(
                        sW + slot * 4096 + row * 16 + kq * 4);
                    const float* src = W + (size_t)(r0c + row) * 1024 + kc + kq * 4;
                    asm volatile("cp.async.cg.shared.global [%0], [%1], 16;"
                                 :: "r"(daddr), "l"(src));
                }
            }
        }
        asm volatile("cp.async.commit_group;" ::: "memory");
    };

    stageW(0); stageW(1); stageW(2);             // 3 groups in flight

    for (int step = 0; step < 64; ++step) {
        if ((step & 7) == 0) {                   // refresh A chunk (128 k)
            __syncthreads();                     // prior chunk fully consumed
            const int kc8 = (step >> 3) << 4;
#pragma unroll
            for (int j = 0; j < 4; ++j) {
                int idx = t + j * 256;
                int row = idx >> 4, c8 = idx & 15;
                sA[row * 17 + c8] = g_x1h4[row * 128 + kc8 + c8];
            }
        }
        asm volatile("cp.async.wait_group 2;" ::: "memory");  // oldest stage done
        __syncthreads();                          // stage + sA visible to all

        const int slot = step & 3;
        const int s = step & 7;
        // W fragment: one LDS.128 per nf (k 4qk..4qk+3 of row r0+nf*8+qr)
        unsigned b0[4], b1[4];
#pragma unroll
        for (int nf = 0; nf < 4; ++nf) {
            float4 wv = *(const float4*)(sW + slot * 4096 +
                                         (w * 32 + nf * 8 + qr) * 16 + qk * 4);
            asm("cvt.rn.bf16x2.f32 %0, %1, %2;" : "=r"(b0[nf]) : "f"(wv.y), "f"(wv.x));
            asm("cvt.rn.bf16x2.f32 %0, %1, %2;" : "=r"(b1[nf]) : "f"(wv.w), "f"(wv.z));
        }
#pragma unroll
        for (int mf = 0; mf < 4; ++mf) {
            const char* base = (const char*)sA + s * 32 + qk * 8;
            uint2 alo = *(const uint2*)(base + (mf * 16 + qr) * 272);
            uint2 ahi = *(const uint2*)(base + (mf * 16 + qr + 8) * 272);
#pragma unroll
            for (int nf = 0; nf < 4; ++nf) {
                asm volatile(
                    "mma.sync.aligned.m16n8k16.row.col.f32.bf16.bf16.f32 "
                    "{%0,%1,%2,%3}, {%4,%5,%6,%7}, {%8,%9}, {%0,%1,%2,%3};"
                    : "+f"(acc[mf][nf][0]), "+f"(acc[mf][nf][1]),
                      "+f"(acc[mf][nf][2]), "+f"(acc[mf][nf][3])
                    : "r"(alo.x), "r"(ahi.x), "r"(alo.y), "r"(ahi.y),
                      "r"(b0[nf]), "r"(b1[nf]));
            }
        }
        stageW(step + 3);                         // keep 3 groups in flight
    }

    // ---- epilogue: bias + store + fused per-row (max, sumexp) partials ----
    float rm[4][2], rs[4][2];
#pragma unroll
    for (int mf = 0; mf < 4; ++mf) { rm[mf][0] = rm[mf][1] = -3.0e38f;
                                     rs[mf][0] = rs[mf][1] = 0.f; }
#pragma unroll
    for (int mf = 0; mf < 4; ++mf) {
        const int m0 = mf * 16 + qr;
#pragma unroll
        for (int nf = 0; nf < 4; ++nf) {
            int rr = r0 + nf * 8 + 2 * qk;
            if (rr < V_) {
                float bv = bias[rr];
                float l0 = acc[mf][nf][0] + bv, l2 = acc[mf][nf][2] + bv;
                out[(size_t)m0 * V_ + rr] = l0;
                out[(size_t)(m0 + 8) * V_ + rr] = l2;
                olmerge(rm[mf][0], rs[mf][0], l0);
                olmerge(rm[mf][1], rs[mf][1], l2);
            }
            if (rr + 1 < V_) {
                float bv = bias[rr + 1];
                float l1 = acc[mf][nf][1] + bv, l3 = acc[mf][nf][3] + bv;
                out[(size_t)m0 * V_ + rr + 1] = l1;
                out[(size_t)(m0 + 8) * V_ + rr + 1] = l3;
                olmerge(rm[mf][0], rs[mf][0], l1);
                olmerge(rm[mf][1], rs[mf][1], l3);
            }
        }
    }
    // reduce across the 4 qk threads of each quad
#pragma unroll
    for (int mf = 0; mf < 4; ++mf)
#pragma unroll
        for (int hf = 0; hf < 2; ++hf) {
#pragma unroll
            for (int o = 1; o <= 2; o <<= 1) {
                float om = __shfl_xor_sync(0xffffffffu, rm[mf][hf], o);
                float os = __shfl_xor_sync(0xffffffffu, rs[mf][hf], o);
                float nm = fmaxf(rm[mf][hf], om);
                rs[mf][hf] = rs[mf][hf] * __expf(rm[mf][hf] - nm) + os * __expf(om - nm);
                rm[mf][hf] = nm;
            }
            if (qk == 0)
                sRed[(mf * 16 + qr + 8 * hf) * 8 + w] = make_float2(rm[mf][hf], rs[mf][hf]);
        }
    __syncthreads();
    if (t < 64) {
        float m = -3.0e38f, s = 0.f;
#pragma unroll
        for (int i = 0; i < 8; ++i) {
            float2 p = sRed[t * 8 + i];
            float nm = fmaxf(m, p.x);
            s = s * __expf(m - nm) + p.y * __expf(p.x - nm);
            m = nm;
        }
        g_pm[(size_t)blockIdx.x * 64 + t] = make_float2(m, s);
    }
}

// =====================================================================
// combine per-CTA lsm partials -> per-row lse (197 partials per row)
// =====================================================================
__global__ __launch_bounds__(256) void k_lsm_comb() {
    const int b = blockIdx.x, t = threadIdx.x;
    __shared__ float redm[8], reds[8];
    float m = -3.0e38f, s = 0.f;
    if (t < NPROJ) {
        float2 p = g_pm[(size_t)t * 64 + b];
        m = p.x; s = p.y;
    }
#pragma unroll
    for (int o = 16; o; o >>= 1) {
        float om = __shfl_xor_sync(0xffffffffu, m, o);
        float os = __shfl_xor_sync(0xffffffffu, s, o);
        float nm = fmaxf(m, om);
        s = s * __expf(m - nm) + os * __expf(om - nm);
        m = nm;
    }
    if ((t & 31) == 0) { redm[t >> 5] = m; reds[t >> 5] = s; }
    __syncthreads();
    if (t == 0) {
        float mm = redm[0], ss = reds[0];
        for (int i = 1; i < 8; ++i) {
            float nm = fmaxf(mm, redm[i]);
            ss = ss * __expf(mm - nm) + reds[i] * __expf(redm[i] - nm);
            mm = nm;
        }
        g_lsmv[b] = mm + logf(ss);
    }
}

// =====================================================================
// subtract lse in place
// =====================================================================
#define LSM_CHUNK 6284   // ceil(50257/8)
__global__ __launch_bounds__(512) void k_lsm2(float* __restrict__ out) {
    const int c = blockIdx.x, b = blockIdx.y, t = threadIdx.x;
    float* row = out + (size_t)b * V_;
    const float lse = g_lsmv[b];
    const int i0 = c * LSM_CHUNK, i1 = min(i0 + LSM_CHUNK, V_);
    for (int i = i0 + t; i < i1; i += 512) row[i] -= lse;
}

// =====================================================================
extern "C" void kernel_launch(void* const* d_in, const int* in_sizes, int n_in,
                              void* d_out, int out_size) {
    const int* ids = (const int*)d_in[0];
    const float* hidden = (const float*)d_in[1];
    const float* baw = (const float*)d_in[2];
    const float* enc = (const float*)d_in[3];
    int o = (n_in >= 5 && in_sizes[4] == 1) ? 1 : 0;
    const float* emb    = (const float*)d_in[4 + o];
    const float* attn_W = (const float*)d_in[5 + o];
    // attn_b (d_in[6+o]) is softmax-shift invariant — unused
    const float* W_ih0  = (const float*)d_in[7 + o];
    const float* W_hh0  = (const float*)d_in[8 + o];
    const float* b_ih0  = (const float*)d_in[9 + o];
    const float* b_hh0  = (const float*)d_in[10 + o];
    const float* W_ih1  = (const float*)d_in[11 + o];
    const float* W_hh1  = (const float*)d_in[12 + o];
    const float* b_ih1  = (const float*)d_in[13 + o];
    const float* b_hh1  = (const float*)d_in[14 + o];
    const float* out_W  = (const float*)d_in[15 + o];
    const float* out_b  = (const float*)d_in[16 + o];
    float* out = (float*)d_out;

    float* p_x0;
    cudaGetSymbolAddress((void**)&p_x0, g_x0);

    const int attn_smem = (64 * 512 + 512 + 64) * 4;  // 133376 B
    cudaFuncSetAttribute(k_attn, cudaFuncAttributeMaxDynamicSharedMemorySize, attn_smem);
    cudaFuncSetAttribute(k_gates, cudaFuncAttributeMaxDynamicSharedMemorySize, GEMM_SMEM_BYTES);
    cudaFuncSetAttribute(k_proj, cudaFuncAttributeMaxDynamicSharedMemorySize, PROJ_SMEM_BYTES);

    // 1. u = h1 @ attn_W (8x8 partials)
    k_u_part<<<dim3(8, 8), 256>>>(hidden, attn_W);
    // 2. per-block attention
    k_attn<<<2048, 512, attn_smem>>>(enc, out);
    // 3. context reduce + embedding gather + concat buffers
    k_ctx<<<64, 512>>>(baw, emb, ids, out);
    // 4. GRU layer 0 gates (k-split 64, r-tile 64), pointwise+reduce
    k_gates<<<dim3(24, 2, 16), 256, GEMM_SMEM_BYTES>>>(p_x0, W_ih0, 1024,
                                                       hidden, W_hh0, 512);
    k_gru<<<64, 512>>>(16, 8, 0, b_ih0, b_hh0, hidden, out + OFF_NH);
    // 5. GRU layer 1 gates, pointwise+reduce (writes x1 bf16)
    k_gates<<<dim3(24, 2, 8), 256, GEMM_SMEM_BYTES>>>(out + OFF_NH, W_ih1, 512,
                                                      hidden + 64 * 512, W_hh1, 512);
    k_gru<<<64, 512>>>(8, 8, 1, b_ih1, b_hh1, hidden + 64 * 512,
                       out + OFF_NH + 64 * 512);
    // 6. output projection (cp.async W pipeline, fused lsm partials)
    k_proj<<<NPROJ, 256, PROJ_SMEM_BYTES>>>(out_W, out_b, out);
    // 7. combine lse + subtract
    k_lsm_comb<<<64, 256>>>();
    k_lsm2<<<dim3(8, 64), 512>>>(out);
}